// round 8
// baseline (speedup 1.0000x reference)
#include <cuda_runtime.h>
#include <math.h>

#define TOKENS 131072
#define CEMB   192
#define NHEAD  6
#define HDIM   32
#define NWIN   2048
#define QSCALE 0.17677669529663687f  // 1/sqrt(32)

// ---------------- scratch (device globals; no runtime allocation) ----------
__device__ float g_xn [(size_t)TOKENS * CEMB];   // LN1(x), window order
__device__ float g_yn [(size_t)TOKENS * CEMB];   // LN1(y), window order
__device__ float g_q  [(size_t)TOKENS * CEMB];   // scaled Q (from y), window order
__device__ float g_kv [(size_t)TOKENS * 2*CEMB]; // [row][0:192]=K, [192:384]=V, window order
__device__ float g_ao [(size_t)TOKENS * CEMB];   // attention out (head-concat), window order
__device__ float g_x1 [(size_t)TOKENS * CEMB];   // x + proj(attn), natural order
__device__ float g_xn2[(size_t)TOKENS * CEMB];   // LN2(x1), natural order
__device__ float g_h  [(size_t)TOKENS * 768];    // MLP hidden
__device__ float g_bias[NHEAD * 64 * 64];        // expanded relative-position bias

// ---------------- LayerNorm (float4, + window permutation) -----------------
__device__ __forceinline__ void warp_sum2(float& s, float& ss) {
#pragma unroll
    for (int o = 16; o; o >>= 1) {
        s  += __shfl_xor_sync(0xffffffffu, s,  o);
        ss += __shfl_xor_sync(0xffffffffu, ss, o);
    }
}

__device__ __forceinline__ void ln_row_f4(
    const float4* __restrict__ in, float4* __restrict__ outp,
    float4 g0, float4 b0, float4 g1, float4 b1, int lane, bool hi)
{
    float4 a = in[lane];
    float4 c = hi ? in[32 + lane] : make_float4(0.f, 0.f, 0.f, 0.f);
    float s  = a.x + a.y + a.z + a.w + c.x + c.y + c.z + c.w;
    float ss = a.x*a.x + a.y*a.y + a.z*a.z + a.w*a.w
             + c.x*c.x + c.y*c.y + c.z*c.z + c.w*c.w;
    warp_sum2(s, ss);
    float mean = s * (1.f/192.f);
    float var  = ss * (1.f/192.f) - mean * mean;
    float r = rsqrtf(var + 1e-5f);
    float4 o;
    o.x = (a.x - mean) * r * g0.x + b0.x;
    o.y = (a.y - mean) * r * g0.y + b0.y;
    o.z = (a.z - mean) * r * g0.z + b0.z;
    o.w = (a.w - mean) * r * g0.w + b0.w;
    outp[lane] = o;
    if (hi) {
        float4 p;
        p.x = (c.x - mean) * r * g1.x + b1.x;
        p.y = (c.y - mean) * r * g1.y + b1.y;
        p.z = (c.z - mean) * r * g1.z + b1.z;
        p.w = (c.w - mean) * r * g1.w + b1.w;
        outp[32 + lane] = p;
    }
}

__global__ void __launch_bounds__(256) ln_perm_kernel(
    const float* __restrict__ x, const float* __restrict__ y,
    const float* __restrict__ g, const float* __restrict__ b,
    float* __restrict__ xn, float* __restrict__ yn)
{
    int token = blockIdx.x * 8 + (threadIdx.x >> 5);
    int lane  = threadIdx.x & 31;
    bool hi = lane < 16;
    int w = token & 63, h = (token >> 6) & 63, d = token >> 12;
    int win  = (((d >> 2) << 4) + (h >> 2)) * 16 + (w >> 2);
    int pos  = ((d & 3) << 4) + ((h & 3) << 2) + (w & 3);
    size_t prow = (size_t)win * 64 + pos;

    const float4* g4 = (const float4*)g;
    const float4* b4 = (const float4*)b;
    float4 g0 = g4[lane], b0 = b4[lane];
    float4 g1 = make_float4(0,0,0,0), b1 = g1;
    if (hi) { g1 = g4[32 + lane]; b1 = b4[32 + lane]; }

    ln_row_f4((const float4*)(x + (size_t)token * CEMB),
              (float4*)(xn + prow * CEMB), g0, b0, g1, b1, lane, hi);
    ln_row_f4((const float4*)(y + (size_t)token * CEMB),
              (float4*)(yn + prow * CEMB), g0, b0, g1, b1, lane, hi);
}

__global__ void __launch_bounds__(256) ln_kernel(
    const float* __restrict__ x, const float* __restrict__ g, const float* __restrict__ b,
    float* __restrict__ xn)
{
    int token = blockIdx.x * 8 + (threadIdx.x >> 5);
    int lane  = threadIdx.x & 31;
    bool hi = lane < 16;
    const float4* g4 = (const float4*)g;
    const float4* b4 = (const float4*)b;
    float4 g0 = g4[lane], b0 = b4[lane];
    float4 g1 = make_float4(0,0,0,0), b1 = g1;
    if (hi) { g1 = g4[32 + lane]; b1 = b4[32 + lane]; }
    ln_row_f4((const float4*)(x + (size_t)token * CEMB),
              (float4*)(xn + (size_t)token * CEMB), g0, b0, g1, b1, lane, hi);
}

// ---------------- bias table expansion (once per call, tiny) ---------------
__global__ void bias_expand_kernel(const float* __restrict__ rpb, float* __restrict__ bias)
{
    int head = blockIdx.x;
    for (int idx = threadIdx.x; idx < 64 * 64; idx += 256) {
        int i = idx >> 6, j = idx & 63;
        int iz = i >> 4, iy = (i >> 2) & 3, ix = i & 3;
        int jz = j >> 4, jy = (j >> 2) & 3, jx = j & 3;
        int ridx = (iz - jz + 3) * 49 + (iy - jy + 3) * 7 + (ix - jx + 3);
        bias[head * 4096 + idx] = rpb[ridx * NHEAD + head];
    }
}

// ---------------- mma helpers ----------------------------------------------
__device__ __forceinline__ float gelu_exact(float v) {
    return 0.5f * v * (1.0f + erff(v * 0.70710678118654752f));
}

__device__ __forceinline__ unsigned pack_bf16(float lo, float hi) {
    unsigned r;
    asm("cvt.rn.bf16x2.f32 %0, %1, %2;" : "=r"(r) : "f"(hi), "f"(lo));
    return r;
}

__device__ __forceinline__ void mma_bf16(float* c, const unsigned* a, const unsigned* b) {
    asm volatile(
        "mma.sync.aligned.m16n8k16.row.col.f32.bf16.bf16.f32 "
        "{%0,%1,%2,%3}, {%4,%5,%6,%7}, {%8,%9}, {%0,%1,%2,%3};"
        : "+f"(c[0]), "+f"(c[1]), "+f"(c[2]), "+f"(c[3])
        : "r"(a[0]), "r"(a[1]), "r"(a[2]), "r"(a[3]), "r"(b[0]), "r"(b[1]));
}

// ---------------- bf16 tensor-core GEMM, double-buffered smem --------------
// CTA tile 128 x (4*WN), BK=32 floats; 256 threads = 8 warps (2x4), warp 64 x WN.
// mode 0: C=(acc+bias)*scale; 1: window->natural permute + resid; 2: gelu; 3: +resid
template<int WN>
__global__ void __launch_bounds__(256) gemm_bf16_kernel(
    const float* __restrict__ A, const float* __restrict__ B,
    const float* __restrict__ bias, const float* __restrict__ resid,
    float* __restrict__ C,
    int K, int ldb, int ldc, float scale, int mode)
{
    constexpr int BN    = WN * 4;
    constexpr int LDB   = BN + 8;                 // ≡8 mod 32 -> conflict-free frag reads
    constexpr int NF    = WN / 8;
    constexpr int BTASK = (16 * (BN / 2)) / 256;  // B float2-pair tasks per thread
    constexpr int ASZ   = 128 * 20;
    constexpr int BSZ   = 16 * LDB;

    __shared__ unsigned As[2][ASZ];   // [buf][row*20 + k2]
    __shared__ unsigned Bs[2][BSZ];   // [buf][k2*LDB + n]

    int tid = threadIdx.x;
    int wid = tid >> 5, lane = tid & 31;
    int g = lane >> 2, t = lane & 3;
    int wm = (wid >> 2) * 64;
    int wn = (wid & 3) * WN;
    size_t rowBase = (size_t)blockIdx.y * 128;
    int nb = blockIdx.x * BN;

    int ar[4], ac[4];
#pragma unroll
    for (int it = 0; it < 4; it++) { int idx = tid + 256*it; ar[it] = idx >> 3; ac[it] = (idx & 7) * 4; }
    int bk2[BTASK], bn0[BTASK];
#pragma unroll
    for (int it = 0; it < BTASK; it++) {
        int task = tid + 256*it;
        bk2[it] = task / (BN/2);
        bn0[it] = (task % (BN/2)) * 2;
    }

    const float* Abase = A + rowBase * (size_t)K;
    float4 pa[4];
    float2 pbe[BTASK], pbo[BTASK];

#pragma unroll
    for (int it = 0; it < 4; it++)
        pa[it] = *(const float4*)(Abase + (size_t)ar[it] * K + ac[it]);
#pragma unroll
    for (int it = 0; it < BTASK; it++) {
        pbe[it] = *(const float2*)(B + (size_t)(2*bk2[it]    ) * ldb + nb + bn0[it]);
        pbo[it] = *(const float2*)(B + (size_t)(2*bk2[it] + 1) * ldb + nb + bn0[it]);
    }

    // stage tile 0 into buffer 0
#pragma unroll
    for (int it = 0; it < 4; it++) {
        uint2 u;
        u.x = pack_bf16(pa[it].x, pa[it].y);
        u.y = pack_bf16(pa[it].z, pa[it].w);
        *(uint2*)&As[0][ar[it]*20 + (ac[it] >> 1)] = u;
    }
#pragma unroll
    for (int it = 0; it < BTASK; it++) {
        uint2 u;
        u.x = pack_bf16(pbe[it].x, pbo[it].x);
        u.y = pack_bf16(pbe[it].y, pbo[it].y);
        *(uint2*)&Bs[0][bk2[it]*LDB + bn0[it]] = u;
    }
    __syncthreads();

    int NIT = K >> 5;
    if (NIT > 1) {
#pragma unroll
        for (int it = 0; it < 4; it++)
            pa[it] = *(const float4*)(Abase + (size_t)ar[it] * K + 32 + ac[it]);
#pragma unroll
        for (int it = 0; it < BTASK; it++) {
            pbe[it] = *(const float2*)(B + (size_t)(32 + 2*bk2[it]    ) * ldb + nb + bn0[it]);
            pbo[it] = *(const float2*)(B + (size_t)(32 + 2*bk2[it] + 1) * ldb + nb + bn0[it]);
        }
    }

    float acc[4][NF][4] = {};

    for (int i = 0; i < NIT; i++) {
        int buf = i & 1;
        if (i + 1 < NIT) {
            int nbuf = buf ^ 1;
#pragma unroll
            for (int it = 0; it < 4; it++) {
                uint2 u;
                u.x = pack_bf16(pa[it].x, pa[it].y);
                u.y = pack_bf16(pa[it].z, pa[it].w);
                *(uint2*)&As[nbuf][ar[it]*20 + (ac[it] >> 1)] = u;
            }
#pragma unroll
            for (int it = 0; it < BTASK; it++) {
                uint2 u;
                u.x = pack_bf16(pbe[it].x, pbo[it].x);
                u.y = pack_bf16(pbe[it].y, pbo[it].y);
                *(uint2*)&Bs[nbuf][bk2[it]*LDB + bn0[it]] = u;
            }
        }

#pragma unroll
        for (int ks = 0; ks < 2; ks++) {
            int kp = ks * 8;
            unsigned bf[NF][2];
#pragma unroll
            for (int nf = 0; nf < NF; nf++) {
                bf[nf][0] = Bs[buf][(kp + t    )*LDB + wn + nf*8 + g];
                bf[nf][1] = Bs[buf][(kp + t + 4)*LDB + wn + nf*8 + g];
            }
#pragma unroll
            for (int mf = 0; mf < 4; mf++) {
                int r0 = wm + mf*16 + g;
                unsigned af[4];
                af[0] = As[buf][(r0    )*20 + kp + t];
                af[1] = As[buf][(r0 + 8)*20 + kp + t];
                af[2] = As[buf][(r0    )*20 + kp + t + 4];
                af[3] = As[buf][(r0 + 8)*20 + kp + t + 4];
#pragma unroll
                for (int nf = 0; nf < NF; nf++) mma_bf16(acc[mf][nf], af, bf[nf]);
            }
        }

        if (i + 1 < NIT) {
            __syncthreads();
            if (i + 2 < NIT) {
                int kn = 32 * (i + 2);
#pragma unroll
                for (int it = 0; it < 4; it++)
                    pa[it] = *(const float4*)(Abase + (size_t)ar[it] * K + kn + ac[it]);
#pragma unroll
                for (int it = 0; it < BTASK; it++) {
                    pbe[it] = *(const float2*)(B + (size_t)(kn + 2*bk2[it]    ) * ldb + nb + bn0[it]);
                    pbo[it] = *(const float2*)(B + (size_t)(kn + 2*bk2[it] + 1) * ldb + nb + bn0[it]);
                }
            }
        }
    }

#pragma unroll
    for (int mf = 0; mf < 4; mf++) {
#pragma unroll
        for (int half = 0; half < 2; half++) {
            size_t row = rowBase + wm + mf*16 + g + half*8;
            size_t orow = row;
            if (mode == 1) {
                int win = (int)(row >> 6), pos = (int)(row & 63);
                int wd = win >> 8, wh = (win >> 4) & 15, ww = win & 15;
                int d = (wd << 2) + (pos >> 4);
                int h = (wh << 2) + ((pos >> 2) & 3);
                int w = (ww << 2) + (pos & 3);
                orow = ((size_t)(d * 64 + h)) * 64 + w;
            }
#pragma unroll
            for (int nf = 0; nf < NF; nf++) {
                int col = nb + wn + nf*8 + 2*t;
                float v0 = acc[mf][nf][half*2+0] + bias[col];
                float v1 = acc[mf][nf][half*2+1] + bias[col+1];
                if (mode == 0) { v0 *= scale; v1 *= scale; }
                else if (mode == 1) {
                    v0 += resid[orow * CEMB + col];
                    v1 += resid[orow * CEMB + col + 1];
                } else if (mode == 2) {
                    v0 = gelu_exact(v0); v1 = gelu_exact(v1);
                } else {
                    v0 += resid[row * CEMB + col];
                    v1 += resid[row * CEMB + col + 1];
                }
                float2 o = make_float2(v0, v1);
                *(float2*)(C + orow * (size_t)ldc + col) = o;
            }
        }
    }
}

// ---------------- bf16 tensor-core windowed cross-attention ----------------
// one block per (window, head); 128 threads (4 warps, 16 rows each)
// K packed in bf16x2 pairs. Qs/Ks stride 20, Vs stride 40, Ps stride 36.
__global__ void __launch_bounds__(128) attn_mma_kernel(
    const float* __restrict__ q, const float* __restrict__ kv,
    const float* __restrict__ bias, float* __restrict__ out)
{
    __shared__ unsigned sm_a[64 * 20 * 2];   // Qs | Ks; reused as Ps[64][36]
    __shared__ unsigned sm_v[32 * 40];

    unsigned (*Qs)[20] = (unsigned(*)[20])sm_a;
    unsigned (*Ks)[20] = (unsigned(*)[20])(sm_a + 64*20);
    unsigned (*Ps)[36] = (unsigned(*)[36])sm_a;   // 64*36 = 2304 <= 2560
    unsigned (*Vs)[40] = (unsigned(*)[40])sm_v;   // [j2][d]

    int win = blockIdx.x, head = blockIdx.y;
    int tid = threadIdx.x;
    int wid = tid >> 5, lane = tid & 31;
    int g = lane >> 2, t = lane & 3;

    const float* qbase = q  + (size_t)win * 64 * CEMB   + head * HDIM;
    const float* kbase = kv + (size_t)win * 64 * 2*CEMB + head * HDIM;
    const float* vbase = kbase + CEMB;

    // load Q,K packed along d; V packed along j
    for (int idx = tid; idx < 64 * 16; idx += 128) {
        int r = idx >> 4, d2 = idx & 15;
        float2 qv = *(const float2*)(qbase + (size_t)r * CEMB   + 2*d2);
        float2 kx = *(const float2*)(kbase + (size_t)r * 2*CEMB + 2*d2);
        Qs[r][d2] = pack_bf16(qv.x, qv.y);
        Ks[r][d2] = pack_bf16(kx.x, kx.y);
    }
    for (int idx = tid; idx < 32 * 32; idx += 128) {
        int j2 = idx >> 5, c = idx & 31;
        Vs[j2][c] = pack_bf16(vbase[(size_t)(2*j2    ) * 2*CEMB + c],
                              vbase[(size_t)(2*j2 + 1) * 2*CEMB + c]);
    }
    __syncthreads();

    // ---- S = Q K^T (64x64x32, bf16) ----
    int r0 = wid * 16;
    float sacc[8][4] = {};
#pragma unroll
    for (int ks = 0; ks < 2; ks++) {
        int kp = ks * 8;
        unsigned af[4];
        af[0] = Qs[r0 + g    ][kp + t];
        af[1] = Qs[r0 + g + 8][kp + t];
        af[2] = Qs[r0 + g    ][kp + t + 4];
        af[3] = Qs[r0 + g + 8][kp + t + 4];
#pragma unroll
        for (int nt = 0; nt < 8; nt++) {
            unsigned bf[2];
            bf[0] = Ks[nt*8 + g][kp + t];
            bf[1] = Ks[nt*8 + g][kp + t + 4];
            mma_bf16(sacc[nt], af, bf);
        }
    }
    __syncthreads();   // all warps done with Qs/Ks before Ps overwrites

    // ---- bias + softmax (rows rA, rB) ----
    int rA = r0 + g, rB = rA + 8;
    const float* bA = bias + head * 4096 + rA * 64;
    const float* bB = bias + head * 4096 + rB * 64;

    float vA[16], vB[16];
    float mA = -1e30f, mB = -1e30f;
#pragma unroll
    for (int nt = 0; nt < 8; nt++) {
#pragma unroll
        for (int e = 0; e < 2; e++) {
            int j = nt*8 + 2*t + e;
            float a = sacc[nt][e]     + bA[j];
            float b = sacc[nt][2 + e] + bB[j];
            vA[nt*2+e] = a; mA = fmaxf(mA, a);
            vB[nt*2+e] = b; mB = fmaxf(mB, b);
        }
    }
    mA = fmaxf(mA, __shfl_xor_sync(0xffffffffu, mA, 1));
    mA = fmaxf(mA, __shfl_xor_sync(0xffffffffu, mA, 2));
    mB = fmaxf(mB, __shfl_xor_sync(0xffffffffu, mB, 1));
    mB = fmaxf(mB, __shfl_xor_sync(0xffffffffu, mB, 2));

    float sA = 0.f, sB = 0.f;
#pragma unroll
    for (int i = 0; i < 16; i++) {
        vA[i] = __expf(vA[i] - mA); sA += vA[i];
        vB[i] = __expf(vB[i] - mB); sB += vB[i];
    }
    sA += __shfl_xor_sync(0xffffffffu, sA, 1);
    sA += __shfl_xor_sync(0xffffffffu, sA, 2);
    sB += __shfl_xor_sync(0xffffffffu, sB, 1);
    sB += __shfl_xor_sync(0xffffffffu, sB, 2);
    float rAi = 1.f / sA, rBi = 1.f / sB;

    // store P packed pairs along j: j = nt*8 + 2t (+1) -> packed col nt*4 + t
#pragma unroll
    for (int nt = 0; nt < 8; nt++) {
        Ps[rA][nt*4 + t] = pack_bf16(vA[nt*2] * rAi, vA[nt*2+1] * rAi);
        Ps[rB][nt*4 + t] = pack_bf16(vB[nt*2] * rBi, vB[nt*2+1] * rBi);
    }
    __syncwarp();   // each warp reads only its own 16 Ps rows

    // ---- O = P V (64x32x64, bf16) ----
    float oacc[4][4] = {};
#pragma unroll
    for (int ks = 0; ks < 4; ks++) {
        int kp = ks * 8;
        unsigned af[4];
        af[0] = Ps[r0 + g    ][kp + t];
        af[1] = Ps[r0 + g + 8][kp + t];
        af[2] = Ps[r0 + g    ][kp + t + 4];
        af[3] = Ps[r0 + g + 8][kp + t + 4];
#pragma unroll
        for (int nt = 0; nt < 4; nt++) {
            unsigned bf[2];
            bf[0] = Vs[kp + t    ][nt*8 + g];
            bf[1] = Vs[kp + t + 4][nt*8 + g];
            mma_bf16(oacc[nt], af, bf);
        }
    }

    float* obase = out + (size_t)win * 64 * CEMB + head * HDIM;
#pragma unroll
    for (int nt = 0; nt < 4; nt++) {
        int c = nt*8 + 2*t;
        *(float2*)&obase[(size_t)rA * CEMB + c] = make_float2(oacc[nt][0], oacc[nt][1]);
        *(float2*)&obase[(size_t)rB * CEMB + c] = make_float2(oacc[nt][2], oacc[nt][3]);
    }
}

// ---------------- launch ----------------------------------------------------
extern "C" void kernel_launch(void* const* d_in, const int* in_sizes, int n_in,
                              void* d_out, int out_size)
{
    const float* x     = (const float*)d_in[0];
    const float* y     = (const float*)d_in[1];
    const float* n1g   = (const float*)d_in[3];
    const float* n1b   = (const float*)d_in[4];
    const float* qkvw  = (const float*)d_in[5];
    const float* qkvb  = (const float*)d_in[6];
    const float* rpb   = (const float*)d_in[7];
    const float* projw = (const float*)d_in[8];
    const float* projb = (const float*)d_in[9];
    const float* n2g   = (const float*)d_in[10];
    const float* n2b   = (const float*)d_in[11];
    const float* fc1w  = (const float*)d_in[12];
    const float* fc1b  = (const float*)d_in[13];
    const float* fc2w  = (const float*)d_in[14];
    const float* fc2b  = (const float*)d_in[15];
    float* out = (float*)d_out;

    float *xn, *yn, *qb, *kvb, *ao, *x1, *xn2, *hb, *bexp;
    cudaGetSymbolAddress((void**)&xn,  g_xn);
    cudaGetSymbolAddress((void**)&yn,  g_yn);
    cudaGetSymbolAddress((void**)&qb,  g_q);
    cudaGetSymbolAddress((void**)&kvb, g_kv);
    cudaGetSymbolAddress((void**)&ao,  g_ao);
    cudaGetSymbolAddress((void**)&x1,  g_x1);
    cudaGetSymbolAddress((void**)&xn2, g_xn2);
    cudaGetSymbolAddress((void**)&hb,  g_h);
    cudaGetSymbolAddress((void**)&bexp, g_bias);

    // 0) expand relative-position bias table (tiny)
    bias_expand_kernel<<<NHEAD, 256>>>(rpb, bexp);

    // 1) LN1 + window permutation for x and y
    ln_perm_kernel<<<TOKENS / 8, 256>>>(x, y, n1g, n1b, xn, yn);

    // 2) Q = (yn @ Wq + bq) * SCALE   (window order)  N=192 -> WN24
    gemm_bf16_kernel<24><<<dim3(2, TOKENS / 128), 256>>>(yn, qkvw, qkvb, nullptr, qb,
                                                         192, 576, 192, QSCALE, 0);
    // 3) KV = xn @ W[k|v] + b         (window order)  N=384 -> WN32
    gemm_bf16_kernel<32><<<dim3(3, TOKENS / 128), 256>>>(xn, qkvw + 192, qkvb + 192, nullptr, kvb,
                                                         192, 576, 384, 1.0f, 0);
    // 4) window attention (bf16 tensor cores)
    attn_mma_kernel<<<dim3(NWIN, NHEAD), 128>>>(qb, kvb, bexp, ao);

    // 5) x1 = x + attn_out @ proj_w + proj_b  (un-permute)  N=192 -> WN24
    gemm_bf16_kernel<24><<<dim3(2, TOKENS / 128), 256>>>(ao, projw, projb, x, x1,
                                                         192, 192, 192, 1.0f, 1);
    // 6) LN2
    ln_kernel<<<TOKENS / 8, 256>>>(x1, n2g, n2b, xn2);

    // 7) h = gelu(xn2 @ fc1_w + fc1_b)   N=768 -> WN32
    gemm_bf16_kernel<32><<<dim3(6, TOKENS / 128), 256>>>(xn2, fc1w, fc1b, nullptr, hb,
                                                         192, 768, 768, 1.0f, 2);
    // 8) out = x1 + h @ fc2_w + fc2_b    N=192 -> WN24
    gemm_bf16_kernel<24><<<dim3(2, TOKENS / 128), 256>>>(hb, fc2w, fc2b, x1, out,
                                                         768, 192, 192, 1.0f, 3);
}

// round 11
// speedup vs baseline: 1.4788x; 1.4788x over previous
#include <cuda_runtime.h>
#include <math.h>

#define TOKENS 131072
#define CEMB   192
#define NHEAD  6
#define HDIM   32
#define NWIN   2048
#define QSCALE 0.17677669529663687f  // 1/sqrt(32)

// ---------------- scratch (device globals; no runtime allocation) ----------
// bf16 stored as packed uint (2 elems). Row length CEMB=192 -> 96 uints.
__device__ unsigned g_xn [(size_t)TOKENS * 96];    // LN1(x), window order, bf16
__device__ unsigned g_yn [(size_t)TOKENS * 96];    // LN1(y), window order, bf16
__device__ unsigned g_q  [(size_t)TOKENS * 96];    // scaled Q, window order, bf16
__device__ unsigned g_kv [(size_t)TOKENS * 192];   // K|V, window order, bf16
__device__ unsigned g_ao [(size_t)TOKENS * 96];    // attn out, window order, bf16
__device__ float    g_x1 [(size_t)TOKENS * CEMB];  // x + proj(attn), natural, fp32
__device__ unsigned g_xn2[(size_t)TOKENS * 96];    // LN2(x1), natural, bf16
__device__ unsigned g_h  [(size_t)TOKENS * 384];   // MLP hidden, bf16
__device__ float    g_bias[NHEAD * 64 * 64];       // expanded rel-pos bias
__device__ unsigned g_w  [221184];                 // all weights bf16: qkv|proj|fc1|fc2

#define WOFF_QKV  0
#define WOFF_PROJ 55296
#define WOFF_FC1  73728
#define WOFF_FC2  147456

// ---------------- helpers ---------------------------------------------------
__device__ __forceinline__ unsigned pack_bf16(float lo, float hi) {
    unsigned r;
    asm("cvt.rn.bf16x2.f32 %0, %1, %2;" : "=r"(r) : "f"(hi), "f"(lo));
    return r;
}

__device__ __forceinline__ float gelu_exact(float v) {
    return 0.5f * v * (1.0f + erff(v * 0.70710678118654752f));
}

__device__ __forceinline__ void mma_bf16(float* c, const unsigned* a, const unsigned* b) {
    asm volatile(
        "mma.sync.aligned.m16n8k16.row.col.f32.bf16.bf16.f32 "
        "{%0,%1,%2,%3}, {%4,%5,%6,%7}, {%8,%9}, {%0,%1,%2,%3};"
        : "+f"(c[0]), "+f"(c[1]), "+f"(c[2]), "+f"(c[3])
        : "r"(a[0]), "r"(a[1]), "r"(a[2]), "r"(a[3]), "r"(b[0]), "r"(b[1]));
}

// ---------------- weight conversion (once per call, tiny) -------------------
__global__ void cvt_w_kernel(const float* __restrict__ src, unsigned* __restrict__ dst, int n2)
{
    int i = blockIdx.x * 256 + threadIdx.x;
    if (i < n2) dst[i] = pack_bf16(src[2*i], src[2*i+1]);
}

// ---------------- bias table expansion --------------------------------------
__global__ void bias_expand_kernel(const float* __restrict__ rpb, float* __restrict__ bias)
{
    int head = blockIdx.x;
    for (int idx = threadIdx.x; idx < 64 * 64; idx += 256) {
        int i = idx >> 6, j = idx & 63;
        int iz = i >> 4, iy = (i >> 2) & 3, ix = i & 3;
        int jz = j >> 4, jy = (j >> 2) & 3, jx = j & 3;
        int ridx = (iz - jz + 3) * 49 + (iy - jy + 3) * 7 + (ix - jx + 3);
        bias[head * 4096 + idx] = rpb[ridx * NHEAD + head];
    }
}

// ---------------- LayerNorm (float4 in, packed bf16 out) --------------------
__device__ __forceinline__ void warp_sum2(float& s, float& ss) {
#pragma unroll
    for (int o = 16; o; o >>= 1) {
        s  += __shfl_xor_sync(0xffffffffu, s,  o);
        ss += __shfl_xor_sync(0xffffffffu, ss, o);
    }
}

// one warp per token: lane handles f4[lane]; lanes<16 also f4[32+lane]
__device__ __forceinline__ void ln_row_f4(
    const float4* __restrict__ in, unsigned* __restrict__ outu,
    float4 g0, float4 b0, float4 g1, float4 b1, int lane, bool hi)
{
    float4 a = in[lane];
    float4 c = hi ? in[32 + lane] : make_float4(0.f, 0.f, 0.f, 0.f);
    float s  = a.x + a.y + a.z + a.w + c.x + c.y + c.z + c.w;
    float ss = a.x*a.x + a.y*a.y + a.z*a.z + a.w*a.w
             + c.x*c.x + c.y*c.y + c.z*c.z + c.w*c.w;
    warp_sum2(s, ss);
    float mean = s * (1.f/192.f);
    float var  = ss * (1.f/192.f) - mean * mean;
    float r = rsqrtf(var + 1e-5f);
    uint2 o;
    o.x = pack_bf16((a.x - mean) * r * g0.x + b0.x, (a.y - mean) * r * g0.y + b0.y);
    o.y = pack_bf16((a.z - mean) * r * g0.z + b0.z, (a.w - mean) * r * g0.w + b0.w);
    *(uint2*)&outu[lane * 2] = o;
    if (hi) {
        uint2 p;
        p.x = pack_bf16((c.x - mean) * r * g1.x + b1.x, (c.y - mean) * r * g1.y + b1.y);
        p.y = pack_bf16((c.z - mean) * r * g1.z + b1.z, (c.w - mean) * r * g1.w + b1.w);
        *(uint2*)&outu[64 + lane * 2] = p;
    }
}

__global__ void __launch_bounds__(256) ln_perm_kernel(
    const float* __restrict__ x, const float* __restrict__ y,
    const float* __restrict__ g, const float* __restrict__ b,
    unsigned* __restrict__ xn, unsigned* __restrict__ yn)
{
    int token = blockIdx.x * 8 + (threadIdx.x >> 5);
    int lane  = threadIdx.x & 31;
    bool hi = lane < 16;
    int w = token & 63, h = (token >> 6) & 63, d = token >> 12;
    int win  = (((d >> 2) << 4) + (h >> 2)) * 16 + (w >> 2);
    int pos  = ((d & 3) << 4) + ((h & 3) << 2) + (w & 3);
    size_t prow = (size_t)win * 64 + pos;

    const float4* g4 = (const float4*)g;
    const float4* b4 = (const float4*)b;
    float4 g0 = g4[lane], b0 = b4[lane];
    float4 g1 = make_float4(0,0,0,0), b1 = g1;
    if (hi) { g1 = g4[32 + lane]; b1 = b4[32 + lane]; }

    ln_row_f4((const float4*)(x + (size_t)token * CEMB), xn + prow * 96,
              g0, b0, g1, b1, lane, hi);
    ln_row_f4((const float4*)(y + (size_t)token * CEMB), yn + prow * 96,
              g0, b0, g1, b1, lane, hi);
}

__global__ void __launch_bounds__(256) ln_kernel(
    const float* __restrict__ x, const float* __restrict__ g, const float* __restrict__ b,
    unsigned* __restrict__ xn)
{
    int token = blockIdx.x * 8 + (threadIdx.x >> 5);
    int lane  = threadIdx.x & 31;
    bool hi = lane < 16;
    const float4* g4 = (const float4*)g;
    const float4* b4 = (const float4*)b;
    float4 g0 = g4[lane], b0 = b4[lane];
    float4 g1 = make_float4(0,0,0,0), b1 = g1;
    if (hi) { g1 = g4[32 + lane]; b1 = b4[32 + lane]; }
    ln_row_f4((const float4*)(x + (size_t)token * CEMB), xn + (size_t)token * 96,
              g0, b0, g1, b1, lane, hi);
}

// ---------------- bf16-in bf16/f32-out tensor-core GEMM ---------------------
// A: bf16 packed [M, K/2] uints. B: bf16 packed [K, N/2] uints (row-major in N).
// CTA tile 128 x (4*WN); 256 threads = 8 warps (2x4), warp 64 x WN. Single-buffer.
// mode 0: bf16 C = (acc+bias)*scale
// mode 1: f32  C[perm(row)] = acc+bias+resid[perm(row)]
// mode 2: bf16 C = gelu(acc+bias)
// mode 3: f32  C = acc+bias+resid[row]
template<int WN>
__global__ void __launch_bounds__(256) gemm_bf16_kernel(
    const unsigned* __restrict__ Au, const unsigned* __restrict__ Bu,
    const float* __restrict__ bias, const float* __restrict__ resid,
    void* __restrict__ Cout,
    int K, int ldb2, int ldc, float scale, int mode)
{
    constexpr int BN  = WN * 4;
    constexpr int LDB = BN + 8;     // uints; ≡8 mod 32 -> conflict-free frag reads
    constexpr int NF  = WN / 8;
    constexpr int NG  = BN / 8;     // B n-groups of 8 columns

    __shared__ unsigned As[128 * 20];   // [row*20 + k2] packed pairs along K
    __shared__ unsigned Bs[16 * LDB];   // [k2*LDB + n]  packed pairs along K

    int tid = threadIdx.x;
    int wid = tid >> 5, lane = tid & 31;
    int g = lane >> 2, t = lane & 3;
    int wm = (wid >> 2) * 64;
    int wn = (wid & 3) * WN;
    size_t rowBase = (size_t)blockIdx.y * 128;
    int nb2 = blockIdx.x * (BN / 2);    // uint col offset into B
    int K2 = K >> 1;

    // A: 2 uint4 tasks/thread over 128 rows x 16 uints
    int ar[2], ac4[2];
#pragma unroll
    for (int it = 0; it < 2; it++) { int idx = tid + 256*it; ar[it] = idx >> 2; ac4[it] = (idx & 3) * 4; }
    const unsigned* Abase = Au + rowBase * K2;

    // B: one task/thread (k2 row, group of 8 columns = 4 source uints)
    bool bact = tid < 16 * NG;
    int bk2 = tid / NG, bng = tid % NG;
    const unsigned* Bb = Bu + nb2 + bng * 4;   // FIX: 8 cols = 4 uints

    uint4 pa[2], pbe, pbo;
#pragma unroll
    for (int it = 0; it < 2; it++)
        pa[it] = *(const uint4*)(Abase + (size_t)ar[it] * K2 + ac4[it]);
    if (bact) {
        pbe = *(const uint4*)(Bb + (size_t)(2*bk2    ) * ldb2);
        pbo = *(const uint4*)(Bb + (size_t)(2*bk2 + 1) * ldb2);
    }

    float acc[4][NF][4] = {};
    int NIT = K >> 5;

    for (int i = 0; i < NIT; i++) {
        // stage current tile
#pragma unroll
        for (int it = 0; it < 2; it++)
            *(uint4*)&As[ar[it]*20 + ac4[it]] = pa[it];
        if (bact) {
            unsigned* d = &Bs[bk2*LDB + bng*8];
            uint4 u0, u1;
            u0.x = __byte_perm(pbe.x, pbo.x, 0x5410); u0.y = __byte_perm(pbe.x, pbo.x, 0x7632);
            u0.z = __byte_perm(pbe.y, pbo.y, 0x5410); u0.w = __byte_perm(pbe.y, pbo.y, 0x7632);
            u1.x = __byte_perm(pbe.z, pbo.z, 0x5410); u1.y = __byte_perm(pbe.z, pbo.z, 0x7632);
            u1.z = __byte_perm(pbe.w, pbo.w, 0x5410); u1.w = __byte_perm(pbe.w, pbo.w, 0x7632);
            *(uint4*)d = u0;
            *(uint4*)(d + 4) = u1;
        }
        __syncthreads();

        // prefetch next tile into regs
        if (i + 1 < NIT) {
            int kn2 = (i + 1) * 16;
#pragma unroll
            for (int it = 0; it < 2; it++)
                pa[it] = *(const uint4*)(Abase + (size_t)ar[it] * K2 + kn2 + ac4[it]);
            if (bact) {
                int kr = (i + 1) * 32 + 2*bk2;
                pbe = *(const uint4*)(Bb + (size_t)kr * ldb2);
                pbo = *(const uint4*)(Bb + (size_t)(kr + 1) * ldb2);
            }
        }

#pragma unroll
        for (int ks = 0; ks < 2; ks++) {
            int kp = ks * 8;
            unsigned bf[NF][2];
#pragma unroll
            for (int nf = 0; nf < NF; nf++) {
                bf[nf][0] = Bs[(kp + t    )*LDB + wn + nf*8 + g];
                bf[nf][1] = Bs[(kp + t + 4)*LDB + wn + nf*8 + g];
            }
#pragma unroll
            for (int mf = 0; mf < 4; mf++) {
                int r0 = wm + mf*16 + g;
                unsigned af[4];
                af[0] = As[(r0    )*20 + kp + t];
                af[1] = As[(r0 + 8)*20 + kp + t];
                af[2] = As[(r0    )*20 + kp + t + 4];
                af[3] = As[(r0 + 8)*20 + kp + t + 4];
#pragma unroll
                for (int nf = 0; nf < NF; nf++) mma_bf16(acc[mf][nf], af, bf[nf]);
            }
        }
        __syncthreads();
    }

    int nbel = nb2 * 2;   // element col offset
#pragma unroll
    for (int mf = 0; mf < 4; mf++) {
#pragma unroll
        for (int half = 0; half < 2; half++) {
            size_t row = rowBase + wm + mf*16 + g + half*8;
            size_t orow = row;
            if (mode == 1) {
                int win = (int)(row >> 6), pos = (int)(row & 63);
                int wd = win >> 8, wh = (win >> 4) & 15, ww = win & 15;
                int d = (wd << 2) + (pos >> 4);
                int h = (wh << 2) + ((pos >> 2) & 3);
                int w = (ww << 2) + (pos & 3);
                orow = ((size_t)(d * 64 + h)) * 64 + w;
            }
#pragma unroll
            for (int nf = 0; nf < NF; nf++) {
                int col = nbel + wn + nf*8 + 2*t;
                float v0 = acc[mf][nf][half*2+0] + bias[col];
                float v1 = acc[mf][nf][half*2+1] + bias[col+1];
                if (mode == 0) {
                    ((unsigned*)Cout)[(orow * (size_t)ldc + col) >> 1] =
                        pack_bf16(v0 * scale, v1 * scale);
                } else if (mode == 2) {
                    ((unsigned*)Cout)[(orow * (size_t)ldc + col) >> 1] =
                        pack_bf16(gelu_exact(v0), gelu_exact(v1));
                } else {
                    const float* rs = resid + (mode == 1 ? orow : row) * CEMB + col;
                    float2 o = make_float2(v0 + rs[0], v1 + rs[1]);
                    *(float2*)((float*)Cout + orow * (size_t)ldc + col) = o;
                }
            }
        }
    }
}

// ---------------- bf16 tensor-core windowed cross-attention -----------------
// one block per (window, head); 128 threads (4 warps, 16 rows each). bf16 I/O.
__global__ void __launch_bounds__(128) attn_mma_kernel(
    const unsigned* __restrict__ qu, const unsigned* __restrict__ kvu,
    const float* __restrict__ bias, unsigned* __restrict__ outu)
{
    __shared__ unsigned sm_a[64 * 20 * 2];   // Qs | Ks; reused as Ps[64][36]
    __shared__ unsigned sm_v[32 * 40];

    unsigned (*Qs)[20] = (unsigned(*)[20])sm_a;
    unsigned (*Ks)[20] = (unsigned(*)[20])(sm_a + 64*20);
    unsigned (*Ps)[36] = (unsigned(*)[36])sm_a;   // 64*36 = 2304 <= 2560
    unsigned (*Vs)[40] = (unsigned(*)[40])sm_v;   // [j2][d], pairs along j

    int win = blockIdx.x, head = blockIdx.y;
    int tid = threadIdx.x;
    int wid = tid >> 5, lane = tid & 31;
    int g = lane >> 2, t = lane & 3;

    const unsigned* qb = qu  + (size_t)win * 64 * 96  + head * 16;
    const unsigned* kb = kvu + (size_t)win * 64 * 192 + head * 16;
    const unsigned* vb = kb + 96;

    // Q,K: pairs along d are contiguous -> raw copies (uint2 per task)
    for (int idx = tid; idx < 64 * 8; idx += 128) {
        int r = idx >> 3, u2 = (idx & 7) * 2;
        *(uint2*)&Qs[r][u2] = *(const uint2*)(qb + (size_t)r * 96  + u2);
        *(uint2*)&Ks[r][u2] = *(const uint2*)(kb + (size_t)r * 192 + u2);
    }
    // V: pairs along j via PRMT of two row words
    for (int idx = tid; idx < 32 * 16; idx += 128) {
        int j2 = idx >> 4, c2 = idx & 15;
        unsigned ue = vb[(size_t)(2*j2    ) * 192 + c2];
        unsigned uo = vb[(size_t)(2*j2 + 1) * 192 + c2];
        Vs[j2][2*c2    ] = __byte_perm(ue, uo, 0x5410);
        Vs[j2][2*c2 + 1] = __byte_perm(ue, uo, 0x7632);
    }
    __syncthreads();

    // ---- S = Q K^T (64x64x32, bf16) ----
    int r0 = wid * 16;
    float sacc[8][4] = {};
#pragma unroll
    for (int ks = 0; ks < 2; ks++) {
        int kp = ks * 8;
        unsigned af[4];
        af[0] = Qs[r0 + g    ][kp + t];
        af[1] = Qs[r0 + g + 8][kp + t];
        af[2] = Qs[r0 + g    ][kp + t + 4];
        af[3] = Qs[r0 + g + 8][kp + t + 4];
#pragma unroll
        for (int nt = 0; nt < 8; nt++) {
            unsigned bf[2];
            bf[0] = Ks[nt*8 + g][kp + t];
            bf[1] = Ks[nt*8 + g][kp + t + 4];
            mma_bf16(sacc[nt], af, bf);
        }
    }
    __syncthreads();   // all warps done with Qs/Ks before Ps overwrites

    // ---- bias + softmax (rows rA, rB) ----
    int rA = r0 + g, rB = rA + 8;
    const float* bA = bias + head * 4096 + rA * 64;
    const float* bB = bias + head * 4096 + rB * 64;

    float vA[16], vB[16];
    float mA = -1e30f, mB = -1e30f;
#pragma unroll
    for (int nt = 0; nt < 8; nt++) {
#pragma unroll
        for (int e = 0; e < 2; e++) {
            int j = nt*8 + 2*t + e;
            float a = sacc[nt][e]     + bA[j];
            float b = sacc[nt][2 + e] + bB[j];
            vA[nt*2+e] = a; mA = fmaxf(mA, a);
            vB[nt*2+e] = b; mB = fmaxf(mB, b);
        }
    }
    mA = fmaxf(mA, __shfl_xor_sync(0xffffffffu, mA, 1));
    mA = fmaxf(mA, __shfl_xor_sync(0xffffffffu, mA, 2));
    mB = fmaxf(mB, __shfl_xor_sync(0xffffffffu, mB, 1));
    mB = fmaxf(mB, __shfl_xor_sync(0xffffffffu, mB, 2));

    float sA = 0.f, sB = 0.f;
#pragma unroll
    for (int i = 0; i < 16; i++) {
        vA[i] = __expf(vA[i] - mA); sA += vA[i];
        vB[i] = __expf(vB[i] - mB); sB += vB[i];
    }
    sA += __shfl_xor_sync(0xffffffffu, sA, 1);
    sA += __shfl_xor_sync(0xffffffffu, sA, 2);
    sB += __shfl_xor_sync(0xffffffffu, sB, 1);
    sB += __shfl_xor_sync(0xffffffffu, sB, 2);
    float rAi = 1.f / sA, rBi = 1.f / sB;

#pragma unroll
    for (int nt = 0; nt < 8; nt++) {
        Ps[rA][nt*4 + t] = pack_bf16(vA[nt*2] * rAi, vA[nt*2+1] * rAi);
        Ps[rB][nt*4 + t] = pack_bf16(vB[nt*2] * rBi, vB[nt*2+1] * rBi);
    }
    __syncwarp();   // each warp reads only its own 16 Ps rows

    // ---- O = P V (64x32x64, bf16) ----
    float oacc[4][4] = {};
#pragma unroll
    for (int ks = 0; ks < 4; ks++) {
        int kp = ks * 8;
        unsigned af[4];
        af[0] = Ps[r0 + g    ][kp + t];
        af[1] = Ps[r0 + g + 8][kp + t];
        af[2] = Ps[r0 + g    ][kp + t + 4];
        af[3] = Ps[r0 + g + 8][kp + t + 4];
#pragma unroll
        for (int nt = 0; nt < 4; nt++) {
            unsigned bf[2];
            bf[0] = Vs[kp + t    ][nt*8 + g];
            bf[1] = Vs[kp + t + 4][nt*8 + g];
            mma_bf16(oacc[nt], af, bf);
        }
    }

    unsigned* ob = outu + (size_t)win * 64 * 96 + head * 16;
#pragma unroll
    for (int nt = 0; nt < 4; nt++) {
        int c2 = nt*4 + t;
        ob[(size_t)rA * 96 + c2] = pack_bf16(oacc[nt][0], oacc[nt][1]);
        ob[(size_t)rB * 96 + c2] = pack_bf16(oacc[nt][2], oacc[nt][3]);
    }
}

// ---------------- launch ----------------------------------------------------
extern "C" void kernel_launch(void* const* d_in, const int* in_sizes, int n_in,
                              void* d_out, int out_size)
{
    const float* x     = (const float*)d_in[0];
    const float* y     = (const float*)d_in[1];
    const float* n1g   = (const float*)d_in[3];
    const float* n1b   = (const float*)d_in[4];
    const float* qkvw  = (const float*)d_in[5];
    const float* qkvb  = (const float*)d_in[6];
    const float* rpb   = (const float*)d_in[7];
    const float* projw = (const float*)d_in[8];
    const float* projb = (const float*)d_in[9];
    const float* n2g   = (const float*)d_in[10];
    const float* n2b   = (const float*)d_in[11];
    const float* fc1w  = (const float*)d_in[12];
    const float* fc1b  = (const float*)d_in[13];
    const float* fc2w  = (const float*)d_in[14];
    const float* fc2b  = (const float*)d_in[15];
    float* out = (float*)d_out;

    unsigned *xn, *yn, *qb, *kvb, *ao, *xn2, *hb, *wbuf;
    float *x1, *bexp;
    cudaGetSymbolAddress((void**)&xn,  g_xn);
    cudaGetSymbolAddress((void**)&yn,  g_yn);
    cudaGetSymbolAddress((void**)&qb,  g_q);
    cudaGetSymbolAddress((void**)&kvb, g_kv);
    cudaGetSymbolAddress((void**)&ao,  g_ao);
    cudaGetSymbolAddress((void**)&x1,  g_x1);
    cudaGetSymbolAddress((void**)&xn2, g_xn2);
    cudaGetSymbolAddress((void**)&hb,  g_h);
    cudaGetSymbolAddress((void**)&bexp, g_bias);
    cudaGetSymbolAddress((void**)&wbuf, g_w);

    // 0) weight conversion + bias expansion (tiny)
    cvt_w_kernel<<<(55296 + 255) / 256, 256>>>(qkvw,  wbuf + WOFF_QKV,  55296);
    cvt_w_kernel<<<(18432 + 255) / 256, 256>>>(projw, wbuf + WOFF_PROJ, 18432);
    cvt_w_kernel<<<(73728 + 255) / 256, 256>>>(fc1w,  wbuf + WOFF_FC1,  73728);
    cvt_w_kernel<<<(73728 + 255) / 256, 256>>>(fc2w,  wbuf + WOFF_FC2,  73728);
    bias_expand_kernel<<<NHEAD, 256>>>(rpb, bexp);

    // 1) LN1 + window permutation (bf16 out)
    ln_perm_kernel<<<TOKENS / 8, 256>>>(x, y, n1g, n1b, xn, yn);

    // 2) Q = (yn @ Wq + bq) * SCALE   -> bf16, N=192 WN24
    gemm_bf16_kernel<24><<<dim3(2, TOKENS / 128), 256>>>(
        yn, wbuf + WOFF_QKV, qkvb, nullptr, qb, 192, 288, 192, QSCALE, 0);
    // 3) KV = xn @ W[k|v] + b         -> bf16, N=384 WN32 (B col offset 192 elems = 96 uints)
    gemm_bf16_kernel<32><<<dim3(3, TOKENS / 128), 256>>>(
        xn, wbuf + WOFF_QKV + 96, qkvb + 192, nullptr, kvb, 192, 288, 384, 1.0f, 0);
    // 4) window attention (bf16 tensor cores)
    attn_mma_kernel<<<dim3(NWIN, NHEAD), 128>>>(qb, kvb, bexp, ao);

    // 5) x1 = x + ao @ proj_w + proj_b  (un-permute) -> fp32, N=192 WN24
    gemm_bf16_kernel<24><<<dim3(2, TOKENS / 128), 256>>>(
        ao, wbuf + WOFF_PROJ, projb, x, x1, 192, 96, 192, 1.0f, 1);
    // 6) LN2 (bf16 out)
    ln_kernel<<<TOKENS / 8, 256>>>(x1, n2g, n2b, xn2);

    // 7) h = gelu(xn2 @ fc1_w + fc1_b)  -> bf16, N=768 WN32
    gemm_bf16_kernel<32><<<dim3(6, TOKENS / 128), 256>>>(
        xn2, wbuf + WOFF_FC1, fc1b, nullptr, hb, 192, 384, 768, 1.0f, 2);
    // 8) out = x1 + h @ fc2_w + fc2_b   -> fp32, N=192 WN24, K=768
    gemm_bf16_kernel<24><<<dim3(2, TOKENS / 128), 256>>>(
        hb, wbuf + WOFF_FC2, fc2b, x1, out, 768, 96, 192, 1.0f, 3);
}

// round 12
// speedup vs baseline: 1.7905x; 1.2108x over previous
#include <cuda_runtime.h>
#include <math.h>

#define TOKENS 131072
#define CEMB   192
#define NHEAD  6
#define HDIM   32
#define NWIN   2048
#define QSCALE 0.17677669529663687f  // 1/sqrt(32)

// ---------------- scratch (device globals; no runtime allocation) ----------
// bf16 stored as packed uint (2 elems). Row length CEMB=192 -> 96 uints.
__device__ unsigned g_xn [(size_t)TOKENS * 96];    // LN1(x), window order, bf16
__device__ unsigned g_yn [(size_t)TOKENS * 96];    // LN1(y), window order, bf16
__device__ unsigned g_q  [(size_t)TOKENS * 96];    // scaled Q, window order, bf16
__device__ unsigned g_kv [(size_t)TOKENS * 192];   // K|V, window order, bf16
__device__ unsigned g_ao [(size_t)TOKENS * 96];    // attn out, window order, bf16
__device__ float    g_x1 [(size_t)TOKENS * CEMB];  // x + proj(attn), natural, fp32
__device__ unsigned g_xn2[(size_t)TOKENS * 96];    // LN2(x1), natural, bf16
__device__ unsigned g_h  [(size_t)TOKENS * 384];   // MLP hidden, bf16
__device__ float    g_bias[NHEAD * 64 * 64];       // expanded rel-pos bias
// weights bf16, PRE-PACKED as [K/2][N] uints: elem(k2,n) = pack(W[2k2][n], W[2k2+1][n])
__device__ unsigned g_w  [221184];                 // qkv|proj|fc1|fc2

#define WOFF_QKV  0
#define WOFF_PROJ 55296
#define WOFF_FC1  73728
#define WOFF_FC2  147456

// ---------------- helpers ---------------------------------------------------
__device__ __forceinline__ unsigned pack_bf16(float lo, float hi) {
    unsigned r;
    asm("cvt.rn.bf16x2.f32 %0, %1, %2;" : "=r"(r) : "f"(hi), "f"(lo));
    return r;
}

__device__ __forceinline__ float gelu_exact(float v) {
    return 0.5f * v * (1.0f + erff(v * 0.70710678118654752f));
}

__device__ __forceinline__ void mma_bf16(float* c, const unsigned* a, const unsigned* b) {
    asm volatile(
        "mma.sync.aligned.m16n8k16.row.col.f32.bf16.bf16.f32 "
        "{%0,%1,%2,%3}, {%4,%5,%6,%7}, {%8,%9}, {%0,%1,%2,%3};"
        : "+f"(c[0]), "+f"(c[1]), "+f"(c[2]), "+f"(c[3])
        : "r"(a[0]), "r"(a[1]), "r"(a[2]), "r"(a[3]), "r"(b[0]), "r"(b[1]));
}

__device__ __forceinline__ void cp16(unsigned* smem_dst, const unsigned* gsrc) {
    unsigned s = (unsigned)__cvta_generic_to_shared(smem_dst);
    asm volatile("cp.async.cg.shared.global [%0], [%1], 16;" :: "r"(s), "l"(gsrc));
}
#define CP_COMMIT() asm volatile("cp.async.commit_group;")
#define CP_WAIT0()  asm volatile("cp.async.wait_group 0;")

// ---------------- weight conversion: pack k-pairs, keep [K2][N] -------------
__global__ void cvt_w_kernel(const float* __restrict__ src, unsigned* __restrict__ dst,
                             int K2, int N)
{
    int i = blockIdx.x * 256 + threadIdx.x;
    if (i < K2 * N) {
        int k2 = i / N, n = i % N;
        dst[i] = pack_bf16(src[(size_t)(2*k2) * N + n], src[(size_t)(2*k2+1) * N + n]);
    }
}

// ---------------- bias table expansion --------------------------------------
__global__ void bias_expand_kernel(const float* __restrict__ rpb, float* __restrict__ bias)
{
    int head = blockIdx.x;
    for (int idx = threadIdx.x; idx < 64 * 64; idx += 256) {
        int i = idx >> 6, j = idx & 63;
        int iz = i >> 4, iy = (i >> 2) & 3, ix = i & 3;
        int jz = j >> 4, jy = (j >> 2) & 3, jx = j & 3;
        int ridx = (iz - jz + 3) * 49 + (iy - jy + 3) * 7 + (ix - jx + 3);
        bias[head * 4096 + idx] = rpb[ridx * NHEAD + head];
    }
}

// ---------------- LayerNorm (float4 in, packed bf16 out) --------------------
__device__ __forceinline__ void warp_sum2(float& s, float& ss) {
#pragma unroll
    for (int o = 16; o; o >>= 1) {
        s  += __shfl_xor_sync(0xffffffffu, s,  o);
        ss += __shfl_xor_sync(0xffffffffu, ss, o);
    }
}

__device__ __forceinline__ void ln_row_f4(
    const float4* __restrict__ in, unsigned* __restrict__ outu,
    float4 g0, float4 b0, float4 g1, float4 b1, int lane, bool hi)
{
    float4 a = in[lane];
    float4 c = hi ? in[32 + lane] : make_float4(0.f, 0.f, 0.f, 0.f);
    float s  = a.x + a.y + a.z + a.w + c.x + c.y + c.z + c.w;
    float ss = a.x*a.x + a.y*a.y + a.z*a.z + a.w*a.w
             + c.x*c.x + c.y*c.y + c.z*c.z + c.w*c.w;
    warp_sum2(s, ss);
    float mean = s * (1.f/192.f);
    float var  = ss * (1.f/192.f) - mean * mean;
    float r = rsqrtf(var + 1e-5f);
    uint2 o;
    o.x = pack_bf16((a.x - mean) * r * g0.x + b0.x, (a.y - mean) * r * g0.y + b0.y);
    o.y = pack_bf16((a.z - mean) * r * g0.z + b0.z, (a.w - mean) * r * g0.w + b0.w);
    *(uint2*)&outu[lane * 2] = o;
    if (hi) {
        uint2 p;
        p.x = pack_bf16((c.x - mean) * r * g1.x + b1.x, (c.y - mean) * r * g1.y + b1.y);
        p.y = pack_bf16((c.z - mean) * r * g1.z + b1.z, (c.w - mean) * r * g1.w + b1.w);
        *(uint2*)&outu[64 + lane * 2] = p;
    }
}

__global__ void __launch_bounds__(256) ln_perm_kernel(
    const float* __restrict__ x, const float* __restrict__ y,
    const float* __restrict__ g, const float* __restrict__ b,
    unsigned* __restrict__ xn, unsigned* __restrict__ yn)
{
    int token = blockIdx.x * 8 + (threadIdx.x >> 5);
    int lane  = threadIdx.x & 31;
    bool hi = lane < 16;
    int w = token & 63, h = (token >> 6) & 63, d = token >> 12;
    int win  = (((d >> 2) << 4) + (h >> 2)) * 16 + (w >> 2);
    int pos  = ((d & 3) << 4) + ((h & 3) << 2) + (w & 3);
    size_t prow = (size_t)win * 64 + pos;

    const float4* g4 = (const float4*)g;
    const float4* b4 = (const float4*)b;
    float4 g0 = g4[lane], b0 = b4[lane];
    float4 g1 = make_float4(0,0,0,0), b1 = g1;
    if (hi) { g1 = g4[32 + lane]; b1 = b4[32 + lane]; }

    ln_row_f4((const float4*)(x + (size_t)token * CEMB), xn + prow * 96,
              g0, b0, g1, b1, lane, hi);
    ln_row_f4((const float4*)(y + (size_t)token * CEMB), yn + prow * 96,
              g0, b0, g1, b1, lane, hi);
}

__global__ void __launch_bounds__(256) ln_kernel(
    const float* __restrict__ x, const float* __restrict__ g, const float* __restrict__ b,
    unsigned* __restrict__ xn)
{
    int token = blockIdx.x * 8 + (threadIdx.x >> 5);
    int lane  = threadIdx.x & 31;
    bool hi = lane < 16;
    const float4* g4 = (const float4*)g;
    const float4* b4 = (const float4*)b;
    float4 g0 = g4[lane], b0 = b4[lane];
    float4 g1 = make_float4(0,0,0,0), b1 = g1;
    if (hi) { g1 = g4[32 + lane]; b1 = b4[32 + lane]; }
    ln_row_f4((const float4*)(x + (size_t)token * CEMB), xn + (size_t)token * 96,
              g0, b0, g1, b1, lane, hi);
}

// ---------------- bf16 GEMM, cp.async double-buffered -----------------------
// A: bf16 packed [M, K/2] uints. B: bf16 PRE-PACKED [K/2, N] uints (k-pairs).
// CTA tile 128 x (4*WN); 256 threads = 8 warps (2x4), warp 64 x WN.
// mode 0: bf16 C=(acc+bias)*scale; 1: f32 C[perm]=..+resid; 2: bf16 gelu; 3: f32 +resid
template<int WN>
__global__ void __launch_bounds__(256) gemm_bf16_kernel(
    const unsigned* __restrict__ Au, const unsigned* __restrict__ Bu,
    const float* __restrict__ bias, const float* __restrict__ resid,
    void* __restrict__ Cout,
    int K, int ldb2, int ldc, float scale, int mode)
{
    constexpr int BN  = WN * 4;
    constexpr int LDB = BN + 8;       // uints; ≡8 mod 32 -> conflict-free frag reads
    constexpr int NF  = WN / 8;
    constexpr int NBC = 16 * (BN / 4);  // B 16-byte chunks per tile

    __shared__ unsigned As[2][128 * 20];   // [buf][row*20 + k2]
    __shared__ unsigned Bs[2][16 * LDB];   // [buf][k2*LDB + n]

    int tid = threadIdx.x;
    int wid = tid >> 5, lane = tid & 31;
    int g = lane >> 2, t = lane & 3;
    int wm = (wid >> 2) * 64;
    int wn = (wid & 3) * WN;
    size_t rowBase = (size_t)blockIdx.y * 128;
    int nb = blockIdx.x * BN;          // element (=uint) col offset into B
    int K2 = K >> 1;

    // A: 2 chunk tasks/thread (128 rows x 4 chunks = 512)
    int ar[2], ac4[2];
#pragma unroll
    for (int it = 0; it < 2; it++) { int idx = tid + 256*it; ar[it] = idx >> 2; ac4[it] = (idx & 3) * 4; }
    const unsigned* Abase = Au + rowBase * K2;
    const unsigned* Bbase = Bu + nb;

    int NIT = K >> 5;

    // prologue: stage tile 0 into buf 0
    {
#pragma unroll
        for (int it = 0; it < 2; it++)
            cp16(&As[0][ar[it]*20 + ac4[it]], Abase + (size_t)ar[it] * K2 + ac4[it]);
        for (int t2 = tid; t2 < NBC; t2 += 256) {
            int br = t2 / (BN/4), bc = (t2 % (BN/4)) * 4;
            cp16(&Bs[0][br*LDB + bc], Bbase + (size_t)br * ldb2 + bc);
        }
        CP_COMMIT();
        CP_WAIT0();
        __syncthreads();
    }

    float acc[4][NF][4] = {};

    for (int i = 0; i < NIT; i++) {
        int buf = i & 1;
        if (i + 1 < NIT) {
            int nbuf = buf ^ 1;
            int kn2 = (i + 1) * 16;
#pragma unroll
            for (int it = 0; it < 2; it++)
                cp16(&As[nbuf][ar[it]*20 + ac4[it]], Abase + (size_t)ar[it] * K2 + kn2 + ac4[it]);
            for (int t2 = tid; t2 < NBC; t2 += 256) {
                int br = t2 / (BN/4), bc = (t2 % (BN/4)) * 4;
                cp16(&Bs[nbuf][br*LDB + bc], Bbase + (size_t)(kn2 + br) * ldb2 + bc);
            }
            CP_COMMIT();
        }

#pragma unroll
        for (int ks = 0; ks < 2; ks++) {
            int kp = ks * 8;
            unsigned bf[NF][2];
#pragma unroll
            for (int nf = 0; nf < NF; nf++) {
                bf[nf][0] = Bs[buf][(kp + t    )*LDB + wn + nf*8 + g];
                bf[nf][1] = Bs[buf][(kp + t + 4)*LDB + wn + nf*8 + g];
            }
#pragma unroll
            for (int mf = 0; mf < 4; mf++) {
                int r0 = wm + mf*16 + g;
                unsigned af[4];
                af[0] = As[buf][(r0    )*20 + kp + t];
                af[1] = As[buf][(r0 + 8)*20 + kp + t];
                af[2] = As[buf][(r0    )*20 + kp + t + 4];
                af[3] = As[buf][(r0 + 8)*20 + kp + t + 4];
#pragma unroll
                for (int nf = 0; nf < NF; nf++) mma_bf16(acc[mf][nf], af, bf[nf]);
            }
        }

        if (i + 1 < NIT) {
            CP_WAIT0();
            __syncthreads();
        }
    }

#pragma unroll
    for (int mf = 0; mf < 4; mf++) {
#pragma unroll
        for (int half = 0; half < 2; half++) {
            size_t row = rowBase + wm + mf*16 + g + half*8;
            size_t orow = row;
            if (mode == 1) {
                int win = (int)(row >> 6), pos = (int)(row & 63);
                int wd = win >> 8, wh = (win >> 4) & 15, ww = win & 15;
                int d = (wd << 2) + (pos >> 4);
                int h = (wh << 2) + ((pos >> 2) & 3);
                int w = (ww << 2) + (pos & 3);
                orow = ((size_t)(d * 64 + h)) * 64 + w;
            }
#pragma unroll
            for (int nf = 0; nf < NF; nf++) {
                int col = nb + wn + nf*8 + 2*t;
                float v0 = acc[mf][nf][half*2+0] + bias[col];
                float v1 = acc[mf][nf][half*2+1] + bias[col+1];
                if (mode == 0) {
                    ((unsigned*)Cout)[(orow * (size_t)ldc + col) >> 1] =
                        pack_bf16(v0 * scale, v1 * scale);
                } else if (mode == 2) {
                    ((unsigned*)Cout)[(orow * (size_t)ldc + col) >> 1] =
                        pack_bf16(gelu_exact(v0), gelu_exact(v1));
                } else {
                    const float* rs = resid + (mode == 1 ? orow : row) * CEMB + col;
                    float2 o = make_float2(v0 + rs[0], v1 + rs[1]);
                    *(float2*)((float*)Cout + orow * (size_t)ldc + col) = o;
                }
            }
        }
    }
}

// ---------------- bf16 tensor-core windowed cross-attention -----------------
// one block per (window, head); 128 threads (4 warps, 16 rows each). bf16 I/O.
__global__ void __launch_bounds__(128) attn_mma_kernel(
    const unsigned* __restrict__ qu, const unsigned* __restrict__ kvu,
    const float* __restrict__ bias, unsigned* __restrict__ outu)
{
    __shared__ unsigned sm_a[64 * 20 * 2];   // Qs | Ks; reused as Ps[64][36]
    __shared__ unsigned sm_v[32 * 40];

    unsigned (*Qs)[20] = (unsigned(*)[20])sm_a;
    unsigned (*Ks)[20] = (unsigned(*)[20])(sm_a + 64*20);
    unsigned (*Ps)[36] = (unsigned(*)[36])sm_a;   // 64*36 = 2304 <= 2560
    unsigned (*Vs)[40] = (unsigned(*)[40])sm_v;   // [j2][d], pairs along j

    int win = blockIdx.x, head = blockIdx.y;
    int tid = threadIdx.x;
    int wid = tid >> 5, lane = tid & 31;
    int g = lane >> 2, t = lane & 3;

    const unsigned* qb = qu  + (size_t)win * 64 * 96  + head * 16;
    const unsigned* kb = kvu + (size_t)win * 64 * 192 + head * 16;
    const unsigned* vb = kb + 96;

    // Q,K: pairs along d are contiguous -> raw copies (uint2 per task)
    for (int idx = tid; idx < 64 * 8; idx += 128) {
        int r = idx >> 3, u2 = (idx & 7) * 2;
        *(uint2*)&Qs[r][u2] = *(const uint2*)(qb + (size_t)r * 96  + u2);
        *(uint2*)&Ks[r][u2] = *(const uint2*)(kb + (size_t)r * 192 + u2);
    }
    // V: pairs along j via PRMT of two row words
    for (int idx = tid; idx < 32 * 16; idx += 128) {
        int j2 = idx >> 4, c2 = idx & 15;
        unsigned ue = vb[(size_t)(2*j2    ) * 192 + c2];
        unsigned uo = vb[(size_t)(2*j2 + 1) * 192 + c2];
        Vs[j2][2*c2    ] = __byte_perm(ue, uo, 0x5410);
        Vs[j2][2*c2 + 1] = __byte_perm(ue, uo, 0x7632);
    }
    __syncthreads();

    // ---- S = Q K^T (64x64x32, bf16) ----
    int r0 = wid * 16;
    float sacc[8][4] = {};
#pragma unroll
    for (int ks = 0; ks < 2; ks++) {
        int kp = ks * 8;
        unsigned af[4];
        af[0] = Qs[r0 + g    ][kp + t];
        af[1] = Qs[r0 + g + 8][kp + t];
        af[2] = Qs[r0 + g    ][kp + t + 4];
        af[3] = Qs[r0 + g + 8][kp + t + 4];
#pragma unroll
        for (int nt = 0; nt < 8; nt++) {
            unsigned bf[2];
            bf[0] = Ks[nt*8 + g][kp + t];
            bf[1] = Ks[nt*8 + g][kp + t + 4];
            mma_bf16(sacc[nt], af, bf);
        }
    }
    __syncthreads();   // all warps done with Qs/Ks before Ps overwrites

    // ---- bias + softmax (rows rA, rB) ----
    int rA = r0 + g, rB = rA + 8;
    const float* bA = bias + head * 4096 + rA * 64;
    const float* bB = bias + head * 4096 + rB * 64;

    float vA[16], vB[16];
    float mA = -1e30f, mB = -1e30f;
#pragma unroll
    for (int nt = 0; nt < 8; nt++) {
#pragma unroll
        for (int e = 0; e < 2; e++) {
            int j = nt*8 + 2*t + e;
            float a = sacc[nt][e]     + bA[j];
            float b = sacc[nt][2 + e] + bB[j];
            vA[nt*2+e] = a; mA = fmaxf(mA, a);
            vB[nt*2+e] = b; mB = fmaxf(mB, b);
        }
    }
    mA = fmaxf(mA, __shfl_xor_sync(0xffffffffu, mA, 1));
    mA = fmaxf(mA, __shfl_xor_sync(0xffffffffu, mA, 2));
    mB = fmaxf(mB, __shfl_xor_sync(0xffffffffu, mB, 1));
    mB = fmaxf(mB, __shfl_xor_sync(0xffffffffu, mB, 2));

    float sA = 0.f, sB = 0.f;
#pragma unroll
    for (int i = 0; i < 16; i++) {
        vA[i] = __expf(vA[i] - mA); sA += vA[i];
        vB[i] = __expf(vB[i] - mB); sB += vB[i];
    }
    sA += __shfl_xor_sync(0xffffffffu, sA, 1);
    sA += __shfl_xor_sync(0xffffffffu, sA, 2);
    sB += __shfl_xor_sync(0xffffffffu, sB, 1);
    sB += __shfl_xor_sync(0xffffffffu, sB, 2);
    float rAi = 1.f / sA, rBi = 1.f / sB;

#pragma unroll
    for (int nt = 0; nt < 8; nt++) {
        Ps[rA][nt*4 + t] = pack_bf16(vA[nt*2] * rAi, vA[nt*2+1] * rAi);
        Ps[rB][nt*4 + t] = pack_bf16(vB[nt*2] * rBi, vB[nt*2+1] * rBi);
    }
    __syncwarp();   // each warp reads only its own 16 Ps rows

    // ---- O = P V (64x32x64, bf16) ----
    float oacc[4][4] = {};
#pragma unroll
    for (int ks = 0; ks < 4; ks++) {
        int kp = ks * 8;
        unsigned af[4];
        af[0] = Ps[r0 + g    ][kp + t];
        af[1] = Ps[r0 + g + 8][kp + t];
        af[2] = Ps[r0 + g    ][kp + t + 4];
        af[3] = Ps[r0 + g + 8][kp + t + 4];
#pragma unroll
        for (int nt = 0; nt < 4; nt++) {
            unsigned bf[2];
            bf[0] = Vs[kp + t    ][nt*8 + g];
            bf[1] = Vs[kp + t + 4][nt*8 + g];
            mma_bf16(oacc[nt], af, bf);
        }
    }

    unsigned* ob = outu + (size_t)win * 64 * 96 + head * 16;
#pragma unroll
    for (int nt = 0; nt < 4; nt++) {
        int c2 = nt*4 + t;
        ob[(size_t)rA * 96 + c2] = pack_bf16(oacc[nt][0], oacc[nt][1]);
        ob[(size_t)rB * 96 + c2] = pack_bf16(oacc[nt][2], oacc[nt][3]);
    }
}

// ---------------- launch ----------------------------------------------------
extern "C" void kernel_launch(void* const* d_in, const int* in_sizes, int n_in,
                              void* d_out, int out_size)
{
    const float* x     = (const float*)d_in[0];
    const float* y     = (const float*)d_in[1];
    const float* n1g   = (const float*)d_in[3];
    const float* n1b   = (const float*)d_in[4];
    const float* qkvw  = (const float*)d_in[5];
    const float* qkvb  = (const float*)d_in[6];
    const float* rpb   = (const float*)d_in[7];
    const float* projw = (const float*)d_in[8];
    const float* projb = (const float*)d_in[9];
    const float* n2g   = (const float*)d_in[10];
    const float* n2b   = (const float*)d_in[11];
    const float* fc1w  = (const float*)d_in[12];
    const float* fc1b  = (const float*)d_in[13];
    const float* fc2w  = (const float*)d_in[14];
    const float* fc2b  = (const float*)d_in[15];
    float* out = (float*)d_out;

    unsigned *xn, *yn, *qb, *kvb, *ao, *xn2, *hb, *wbuf;
    float *x1, *bexp;
    cudaGetSymbolAddress((void**)&xn,  g_xn);
    cudaGetSymbolAddress((void**)&yn,  g_yn);
    cudaGetSymbolAddress((void**)&qb,  g_q);
    cudaGetSymbolAddress((void**)&kvb, g_kv);
    cudaGetSymbolAddress((void**)&ao,  g_ao);
    cudaGetSymbolAddress((void**)&x1,  g_x1);
    cudaGetSymbolAddress((void**)&xn2, g_xn2);
    cudaGetSymbolAddress((void**)&hb,  g_h);
    cudaGetSymbolAddress((void**)&bexp, g_bias);
    cudaGetSymbolAddress((void**)&wbuf, g_w);

    // 0) weight conversion (k-pair packing, [K2][N]) + bias expansion (tiny)
    cvt_w_kernel<<<(55296 + 255) / 256, 256>>>(qkvw,  wbuf + WOFF_QKV,  96, 576);
    cvt_w_kernel<<<(18432 + 255) / 256, 256>>>(projw, wbuf + WOFF_PROJ, 96, 192);
    cvt_w_kernel<<<(73728 + 255) / 256, 256>>>(fc1w,  wbuf + WOFF_FC1,  96, 768);
    cvt_w_kernel<<<(73728 + 255) / 256, 256>>>(fc2w,  wbuf + WOFF_FC2,  384, 192);
    bias_expand_kernel<<<NHEAD, 256>>>(rpb, bexp);

    // 1) LN1 + window permutation (bf16 out)
    ln_perm_kernel<<<TOKENS / 8, 256>>>(x, y, n1g, n1b, xn, yn);

    // 2) Q = (yn @ Wq + bq) * SCALE   -> bf16, N=192 WN24
    gemm_bf16_kernel<24><<<dim3(2, TOKENS / 128), 256>>>(
        yn, wbuf + WOFF_QKV, qkvb, nullptr, qb, 192, 576, 192, QSCALE, 0);
    // 3) KV = xn @ W[k|v] + b         -> bf16, N=384 WN32 (B col offset 192 uints)
    gemm_bf16_kernel<32><<<dim3(3, TOKENS / 128), 256>>>(
        xn, wbuf + WOFF_QKV + 192, qkvb + 192, nullptr, kvb, 192, 576, 384, 1.0f, 0);
    // 4) window attention (bf16 tensor cores)
    attn_mma_kernel<<<dim3(NWIN, NHEAD), 128>>>(qb, kvb, bexp, ao);

    // 5) x1 = x + ao @ proj_w + proj_b  (un-permute) -> fp32, N=192 WN24
    gemm_bf16_kernel<24><<<dim3(2, TOKENS / 128), 256>>>(
        ao, wbuf + WOFF_PROJ, projb, x, x1, 192, 192, 192, 1.0f, 1);
    // 6) LN2 (bf16 out)
    ln_kernel<<<TOKENS / 8, 256>>>(x1, n2g, n2b, xn2);

    // 7) h = gelu(xn2 @ fc1_w + fc1_b)  -> bf16, N=768 WN32
    gemm_bf16_kernel<32><<<dim3(6, TOKENS / 128), 256>>>(
        xn2, wbuf + WOFF_FC1, fc1b, nullptr, hb, 192, 768, 768, 1.0f, 2);
    // 8) out = x1 + h @ fc2_w + fc2_b   -> fp32, N=192 WN24, K=768
    gemm_bf16_kernel<24><<<dim3(2, TOKENS / 128), 256>>>(
        hb, wbuf + WOFF_FC2, fc2b, x1, out, 768, 192, 192, 1.0f, 3);
}

// round 13
// speedup vs baseline: 1.8319x; 1.0231x over previous
#include <cuda_runtime.h>
#include <math.h>

#define TOKENS 131072
#define CEMB   192
#define NHEAD  6
#define HDIM   32
#define NWIN   2048
#define QSCALE 0.17677669529663687f  // 1/sqrt(32)

// ---------------- scratch (device globals; no runtime allocation) ----------
__device__ unsigned g_xn [(size_t)TOKENS * 96];    // LN1(x), window order, bf16
__device__ unsigned g_yn [(size_t)TOKENS * 96];    // LN1(y), window order, bf16
__device__ unsigned g_q  [(size_t)TOKENS * 96];    // scaled Q, window order, bf16
__device__ unsigned g_kv [(size_t)TOKENS * 192];   // K|V, window order, bf16
__device__ unsigned g_ao [(size_t)TOKENS * 96];    // attn out, window order, bf16
__device__ float    g_x1 [(size_t)TOKENS * CEMB];  // x + proj(attn), natural, fp32
__device__ unsigned g_xn2[(size_t)TOKENS * 96];    // LN2(x1), natural, bf16
__device__ unsigned g_h  [(size_t)TOKENS * 384];   // MLP hidden, bf16
__device__ float    g_bias[NHEAD * 64 * 64];       // expanded rel-pos bias
// weights bf16, PRE-PACKED as [K/2][N] uints: elem(k2,n) = pack(W[2k2][n], W[2k2+1][n])
__device__ unsigned g_w  [221184];                 // qkv|proj|fc1|fc2

#define WOFF_QKV  0
#define WOFF_PROJ 55296
#define WOFF_FC1  73728
#define WOFF_FC2  147456

// ---------------- helpers ---------------------------------------------------
__device__ __forceinline__ unsigned pack_bf16(float lo, float hi) {
    unsigned r;
    asm("cvt.rn.bf16x2.f32 %0, %1, %2;" : "=r"(r) : "f"(hi), "f"(lo));
    return r;
}

__device__ __forceinline__ float gelu_exact(float v) {
    return 0.5f * v * (1.0f + erff(v * 0.70710678118654752f));
}

__device__ __forceinline__ void mma_bf16(float* c, const unsigned* a, const unsigned* b) {
    asm volatile(
        "mma.sync.aligned.m16n8k16.row.col.f32.bf16.bf16.f32 "
        "{%0,%1,%2,%3}, {%4,%5,%6,%7}, {%8,%9}, {%0,%1,%2,%3};"
        : "+f"(c[0]), "+f"(c[1]), "+f"(c[2]), "+f"(c[3])
        : "r"(a[0]), "r"(a[1]), "r"(a[2]), "r"(a[3]), "r"(b[0]), "r"(b[1]));
}

__device__ __forceinline__ void ldsm_x4(unsigned* r, const unsigned* smem_ptr) {
    unsigned addr = (unsigned)__cvta_generic_to_shared(smem_ptr);
    asm volatile("ldmatrix.sync.aligned.m8n8.x4.shared.b16 {%0,%1,%2,%3}, [%4];"
                 : "=r"(r[0]), "=r"(r[1]), "=r"(r[2]), "=r"(r[3]) : "r"(addr));
}

__device__ __forceinline__ void cp16(unsigned* smem_dst, const unsigned* gsrc) {
    unsigned s = (unsigned)__cvta_generic_to_shared(smem_dst);
    asm volatile("cp.async.cg.shared.global [%0], [%1], 16;" :: "r"(s), "l"(gsrc));
}
#define CP_COMMIT() asm volatile("cp.async.commit_group;")
#define CP_WAIT0()  asm volatile("cp.async.wait_group 0;")

// ---------------- fused weight conversion (one launch) ----------------------
__global__ void cvt_all_kernel(const float* __restrict__ qkvw, const float* __restrict__ projw,
                               const float* __restrict__ fc1w, const float* __restrict__ fc2w,
                               unsigned* __restrict__ dst)
{
    int i = blockIdx.x * 256 + threadIdx.x;
    const float* src; int N, base;
    if (i < 55296)       { src = qkvw;  N = 576; base = 0; }
    else if (i < 73728)  { src = projw; N = 192; base = 55296; }
    else if (i < 147456) { src = fc1w;  N = 768; base = 73728; }
    else if (i < 221184) { src = fc2w;  N = 192; base = 147456; }
    else return;
    int j = i - base;
    int k2 = j / N, n = j % N;
    dst[i] = pack_bf16(src[(size_t)(2*k2) * N + n], src[(size_t)(2*k2+1) * N + n]);
}

// ---------------- bias table expansion --------------------------------------
__global__ void bias_expand_kernel(const float* __restrict__ rpb, float* __restrict__ bias)
{
    int head = blockIdx.x;
    for (int idx = threadIdx.x; idx < 64 * 64; idx += 256) {
        int i = idx >> 6, j = idx & 63;
        int iz = i >> 4, iy = (i >> 2) & 3, ix = i & 3;
        int jz = j >> 4, jy = (j >> 2) & 3, jx = j & 3;
        int ridx = (iz - jz + 3) * 49 + (iy - jy + 3) * 7 + (ix - jx + 3);
        bias[head * 4096 + idx] = rpb[ridx * NHEAD + head];
    }
}

// ---------------- LayerNorm (float4 in, packed bf16 out) --------------------
__device__ __forceinline__ void warp_sum2(float& s, float& ss) {
#pragma unroll
    for (int o = 16; o; o >>= 1) {
        s  += __shfl_xor_sync(0xffffffffu, s,  o);
        ss += __shfl_xor_sync(0xffffffffu, ss, o);
    }
}

__device__ __forceinline__ void ln_row_f4(
    const float4* __restrict__ in, unsigned* __restrict__ outu,
    float4 g0, float4 b0, float4 g1, float4 b1, int lane, bool hi)
{
    float4 a = in[lane];
    float4 c = hi ? in[32 + lane] : make_float4(0.f, 0.f, 0.f, 0.f);
    float s  = a.x + a.y + a.z + a.w + c.x + c.y + c.z + c.w;
    float ss = a.x*a.x + a.y*a.y + a.z*a.z + a.w*a.w
             + c.x*c.x + c.y*c.y + c.z*c.z + c.w*c.w;
    warp_sum2(s, ss);
    float mean = s * (1.f/192.f);
    float var  = ss * (1.f/192.f) - mean * mean;
    float r = rsqrtf(var + 1e-5f);
    uint2 o;
    o.x = pack_bf16((a.x - mean) * r * g0.x + b0.x, (a.y - mean) * r * g0.y + b0.y);
    o.y = pack_bf16((a.z - mean) * r * g0.z + b0.z, (a.w - mean) * r * g0.w + b0.w);
    *(uint2*)&outu[lane * 2] = o;
    if (hi) {
        uint2 p;
        p.x = pack_bf16((c.x - mean) * r * g1.x + b1.x, (c.y - mean) * r * g1.y + b1.y);
        p.y = pack_bf16((c.z - mean) * r * g1.z + b1.z, (c.w - mean) * r * g1.w + b1.w);
        *(uint2*)&outu[64 + lane * 2] = p;
    }
}

__global__ void __launch_bounds__(256) ln_perm_kernel(
    const float* __restrict__ x, const float* __restrict__ y,
    const float* __restrict__ g, const float* __restrict__ b,
    unsigned* __restrict__ xn, unsigned* __restrict__ yn)
{
    int token = blockIdx.x * 8 + (threadIdx.x >> 5);
    int lane  = threadIdx.x & 31;
    bool hi = lane < 16;
    int w = token & 63, h = (token >> 6) & 63, d = token >> 12;
    int win  = (((d >> 2) << 4) + (h >> 2)) * 16 + (w >> 2);
    int pos  = ((d & 3) << 4) + ((h & 3) << 2) + (w & 3);
    size_t prow = (size_t)win * 64 + pos;

    const float4* g4 = (const float4*)g;
    const float4* b4 = (const float4*)b;
    float4 g0 = g4[lane], b0 = b4[lane];
    float4 g1 = make_float4(0,0,0,0), b1 = g1;
    if (hi) { g1 = g4[32 + lane]; b1 = b4[32 + lane]; }

    ln_row_f4((const float4*)(x + (size_t)token * CEMB), xn + prow * 96,
              g0, b0, g1, b1, lane, hi);
    ln_row_f4((const float4*)(y + (size_t)token * CEMB), yn + prow * 96,
              g0, b0, g1, b1, lane, hi);
}

__global__ void __launch_bounds__(256) ln_kernel(
    const float* __restrict__ x, const float* __restrict__ g, const float* __restrict__ b,
    unsigned* __restrict__ xn)
{
    int token = blockIdx.x * 8 + (threadIdx.x >> 5);
    int lane  = threadIdx.x & 31;
    bool hi = lane < 16;
    const float4* g4 = (const float4*)g;
    const float4* b4 = (const float4*)b;
    float4 g0 = g4[lane], b0 = b4[lane];
    float4 g1 = make_float4(0,0,0,0), b1 = g1;
    if (hi) { g1 = g4[32 + lane]; b1 = b4[32 + lane]; }
    ln_row_f4((const float4*)(x + (size_t)token * CEMB), xn + (size_t)token * 96,
              g0, b0, g1, b1, lane, hi);
}

// ---------------- bf16 GEMM, cp.async double-buffered + LDSM ----------------
// A: bf16 packed [M, K/2] uints. B: bf16 PRE-PACKED [K/2, N] uints (k-pairs).
// CTA tile 128 x (4*WN); 256 threads = 8 warps (2x4), warp 64 x WN.
// mode 0: bf16 C=(acc+bias)*scale; 1: f32 C[perm]=..+resid; 2: bf16 gelu; 3: f32 +resid
template<int WN>
__global__ void __launch_bounds__(256) gemm_bf16_kernel(
    const unsigned* __restrict__ Au, const unsigned* __restrict__ Bu,
    const float* __restrict__ bias, const float* __restrict__ resid,
    void* __restrict__ Cout,
    int K, int ldb2, int ldc, float scale, int mode)
{
    constexpr int BN  = WN * 4;
    constexpr int LDB = BN + 8;       // uints; ≡8 mod 32 -> conflict-free frag reads
    constexpr int NF  = WN / 8;
    constexpr int NBC = 16 * (BN / 4);  // B 16-byte chunks per tile

    __shared__ unsigned As[2][128 * 20];   // [buf][row*20 + k2]
    __shared__ unsigned Bs[2][16 * LDB];   // [buf][k2*LDB + n]

    int tid = threadIdx.x;
    int wid = tid >> 5, lane = tid & 31;
    int g = lane >> 2, t = lane & 3;
    int wm = (wid >> 2) * 64;
    int wn = (wid & 3) * WN;
    size_t rowBase = (size_t)blockIdx.y * 128;
    int nb = blockIdx.x * BN;
    int K2 = K >> 1;

    // ldmatrix lane constants (A frag: four 8x8 tiles)
    int arow = (lane & 7) + ((lane >> 3) & 1) * 8;
    int acol = ((lane >> 4) & 1) * 4;

    // A staging: 2 chunk tasks/thread (128 rows x 4 chunks = 512)
    int ar[2], ac4[2];
#pragma unroll
    for (int it = 0; it < 2; it++) { int idx = tid + 256*it; ar[it] = idx >> 2; ac4[it] = (idx & 3) * 4; }
    const unsigned* Abase = Au + rowBase * K2;
    const unsigned* Bbase = Bu + nb;

    int NIT = K >> 5;

    // prologue: stage tile 0 into buf 0
    {
#pragma unroll
        for (int it = 0; it < 2; it++)
            cp16(&As[0][ar[it]*20 + ac4[it]], Abase + (size_t)ar[it] * K2 + ac4[it]);
        for (int t2 = tid; t2 < NBC; t2 += 256) {
            int br = t2 / (BN/4), bc = (t2 % (BN/4)) * 4;
            cp16(&Bs[0][br*LDB + bc], Bbase + (size_t)br * ldb2 + bc);
        }
        CP_COMMIT();
        CP_WAIT0();
        __syncthreads();
    }

    float acc[4][NF][4] = {};

    for (int i = 0; i < NIT; i++) {
        int buf = i & 1;
        if (i + 1 < NIT) {
            int nbuf = buf ^ 1;
            int kn2 = (i + 1) * 16;
#pragma unroll
            for (int it = 0; it < 2; it++)
                cp16(&As[nbuf][ar[it]*20 + ac4[it]], Abase + (size_t)ar[it] * K2 + kn2 + ac4[it]);
            for (int t2 = tid; t2 < NBC; t2 += 256) {
                int br = t2 / (BN/4), bc = (t2 % (BN/4)) * 4;
                cp16(&Bs[nbuf][br*LDB + bc], Bbase + (size_t)(kn2 + br) * ldb2 + bc);
            }
            CP_COMMIT();
        }

#pragma unroll
        for (int ks = 0; ks < 2; ks++) {
            int kp = ks * 8;
            unsigned bf[NF][2];
#pragma unroll
            for (int nf = 0; nf < NF; nf++) {
                bf[nf][0] = Bs[buf][(kp + t    )*LDB + wn + nf*8 + g];
                bf[nf][1] = Bs[buf][(kp + t + 4)*LDB + wn + nf*8 + g];
            }
#pragma unroll
            for (int mf = 0; mf < 4; mf++) {
                unsigned af[4];
                ldsm_x4(af, &As[buf][(wm + mf*16 + arow)*20 + kp + acol]);
#pragma unroll
                for (int nf = 0; nf < NF; nf++) mma_bf16(acc[mf][nf], af, bf[nf]);
            }
        }

        if (i + 1 < NIT) {
            CP_WAIT0();
            __syncthreads();
        }
    }

#pragma unroll
    for (int mf = 0; mf < 4; mf++) {
#pragma unroll
        for (int half = 0; half < 2; half++) {
            size_t row = rowBase + wm + mf*16 + g + half*8;
            size_t orow = row;
            if (mode == 1) {
                int win = (int)(row >> 6), pos = (int)(row & 63);
                int wd = win >> 8, wh = (win >> 4) & 15, ww = win & 15;
                int d = (wd << 2) + (pos >> 4);
                int h = (wh << 2) + ((pos >> 2) & 3);
                int w = (ww << 2) + (pos & 3);
                orow = ((size_t)(d * 64 + h)) * 64 + w;
            }
#pragma unroll
            for (int nf = 0; nf < NF; nf++) {
                int col = nb + wn + nf*8 + 2*t;
                float v0 = acc[mf][nf][half*2+0] + bias[col];
                float v1 = acc[mf][nf][half*2+1] + bias[col+1];
                if (mode == 0) {
                    ((unsigned*)Cout)[(orow * (size_t)ldc + col) >> 1] =
                        pack_bf16(v0 * scale, v1 * scale);
                } else if (mode == 2) {
                    ((unsigned*)Cout)[(orow * (size_t)ldc + col) >> 1] =
                        pack_bf16(gelu_exact(v0), gelu_exact(v1));
                } else {
                    const float* rs = resid + (mode == 1 ? orow : row) * CEMB + col;
                    float2 o = make_float2(v0 + rs[0], v1 + rs[1]);
                    *(float2*)((float*)Cout + orow * (size_t)ldc + col) = o;
                }
            }
        }
    }
}

// ---------------- bf16 tensor-core windowed cross-attention -----------------
// one block per (window, head); 128 threads (4 warps, 16 rows each). bf16 I/O.
__global__ void __launch_bounds__(128) attn_mma_kernel(
    const unsigned* __restrict__ qu, const unsigned* __restrict__ kvu,
    const float* __restrict__ bias, unsigned* __restrict__ outu)
{
    __shared__ unsigned sm_a[64 * 20 * 2];   // Qs | Ks; reused as Ps[64][36]
    __shared__ unsigned sm_v[32 * 40];

    unsigned (*Qs)[20] = (unsigned(*)[20])sm_a;
    unsigned (*Ks)[20] = (unsigned(*)[20])(sm_a + 64*20);
    unsigned (*Ps)[36] = (unsigned(*)[36])sm_a;   // 64*36 = 2304 <= 2560
    unsigned (*Vs)[40] = (unsigned(*)[40])sm_v;   // [j2][d], pairs along j

    int win = blockIdx.x, head = blockIdx.y;
    int tid = threadIdx.x;
    int wid = tid >> 5, lane = tid & 31;
    int g = lane >> 2, t = lane & 3;
    int arow = (lane & 7) + ((lane >> 3) & 1) * 8;
    int acol = ((lane >> 4) & 1) * 4;

    const unsigned* qb = qu  + (size_t)win * 64 * 96  + head * 16;
    const unsigned* kb = kvu + (size_t)win * 64 * 192 + head * 16;
    const unsigned* vb = kb + 96;

    // Q,K: pairs along d are contiguous -> raw copies (uint2 per task)
    for (int idx = tid; idx < 64 * 8; idx += 128) {
        int r = idx >> 3, u2 = (idx & 7) * 2;
        *(uint2*)&Qs[r][u2] = *(const uint2*)(qb + (size_t)r * 96  + u2);
        *(uint2*)&Ks[r][u2] = *(const uint2*)(kb + (size_t)r * 192 + u2);
    }
    // V: pairs along j via PRMT of two row words
    for (int idx = tid; idx < 32 * 16; idx += 128) {
        int j2 = idx >> 4, c2 = idx & 15;
        unsigned ue = vb[(size_t)(2*j2    ) * 192 + c2];
        unsigned uo = vb[(size_t)(2*j2 + 1) * 192 + c2];
        Vs[j2][2*c2    ] = __byte_perm(ue, uo, 0x5410);
        Vs[j2][2*c2 + 1] = __byte_perm(ue, uo, 0x7632);
    }
    __syncthreads();

    // ---- S = Q K^T (64x64x32, bf16) ----
    int r0 = wid * 16;
    float sacc[8][4] = {};
#pragma unroll
    for (int ks = 0; ks < 2; ks++) {
        int kp = ks * 8;
        unsigned af[4];
        ldsm_x4(af, &Qs[r0 + arow][kp + acol]);
#pragma unroll
        for (int nt = 0; nt < 8; nt++) {
            unsigned bf[2];
            bf[0] = Ks[nt*8 + g][kp + t];
            bf[1] = Ks[nt*8 + g][kp + t + 4];
            mma_bf16(sacc[nt], af, bf);
        }
    }
    __syncthreads();   // all warps done with Qs/Ks before Ps overwrites

    // ---- bias + softmax (rows rA, rB) ----
    int rA = r0 + g, rB = rA + 8;
    const float* bA = bias + head * 4096 + rA * 64;
    const float* bB = bias + head * 4096 + rB * 64;

    float vA[16], vB[16];
    float mA = -1e30f, mB = -1e30f;
#pragma unroll
    for (int nt = 0; nt < 8; nt++) {
#pragma unroll
        for (int e = 0; e < 2; e++) {
            int j = nt*8 + 2*t + e;
            float a = sacc[nt][e]     + bA[j];
            float b = sacc[nt][2 + e] + bB[j];
            vA[nt*2+e] = a; mA = fmaxf(mA, a);
            vB[nt*2+e] = b; mB = fmaxf(mB, b);
        }
    }
    mA = fmaxf(mA, __shfl_xor_sync(0xffffffffu, mA, 1));
    mA = fmaxf(mA, __shfl_xor_sync(0xffffffffu, mA, 2));
    mB = fmaxf(mB, __shfl_xor_sync(0xffffffffu, mB, 1));
    mB = fmaxf(mB, __shfl_xor_sync(0xffffffffu, mB, 2));

    float sA = 0.f, sB = 0.f;
#pragma unroll
    for (int i = 0; i < 16; i++) {
        vA[i] = __expf(vA[i] - mA); sA += vA[i];
        vB[i] = __expf(vB[i] - mB); sB += vB[i];
    }
    sA += __shfl_xor_sync(0xffffffffu, sA, 1);
    sA += __shfl_xor_sync(0xffffffffu, sA, 2);
    sB += __shfl_xor_sync(0xffffffffu, sB, 1);
    sB += __shfl_xor_sync(0xffffffffu, sB, 2);
    float rAi = 1.f / sA, rBi = 1.f / sB;

#pragma unroll
    for (int nt = 0; nt < 8; nt++) {
        Ps[rA][nt*4 + t] = pack_bf16(vA[nt*2] * rAi, vA[nt*2+1] * rAi);
        Ps[rB][nt*4 + t] = pack_bf16(vB[nt*2] * rBi, vB[nt*2+1] * rBi);
    }
    __syncwarp();   // each warp reads only its own 16 Ps rows

    // ---- O = P V (64x32x64, bf16) ----
    float oacc[4][4] = {};
#pragma unroll
    for (int ks = 0; ks < 4; ks++) {
        int kp = ks * 8;
        unsigned af[4];
        ldsm_x4(af, &Ps[r0 + arow][kp + acol]);
#pragma unroll
        for (int nt = 0; nt < 4; nt++) {
            unsigned bf[2];
            bf[0] = Vs[kp + t    ][nt*8 + g];
            bf[1] = Vs[kp + t + 4][nt*8 + g];
            mma_bf16(oacc[nt], af, bf);
        }
    }

    unsigned* ob = outu + (size_t)win * 64 * 96 + head * 16;
#pragma unroll
    for (int nt = 0; nt < 4; nt++) {
        int c2 = nt*4 + t;
        ob[(size_t)rA * 96 + c2] = pack_bf16(oacc[nt][0], oacc[nt][1]);
        ob[(size_t)rB * 96 + c2] = pack_bf16(oacc[nt][2], oacc[nt][3]);
    }
}

// ---------------- launch ----------------------------------------------------
extern "C" void kernel_launch(void* const* d_in, const int* in_sizes, int n_in,
                              void* d_out, int out_size)
{
    const float* x     = (const float*)d_in[0];
    const float* y     = (const float*)d_in[1];
    const float* n1g   = (const float*)d_in[3];
    const float* n1b   = (const float*)d_in[4];
    const float* qkvw  = (const float*)d_in[5];
    const float* qkvb  = (const float*)d_in[6];
    const float* rpb   = (const float*)d_in[7];
    const float* projw = (const float*)d_in[8];
    const float* projb = (const float*)d_in[9];
    const float* n2g   = (const float*)d_in[10];
    const float* n2b   = (const float*)d_in[11];
    const float* fc1w  = (const float*)d_in[12];
    const float* fc1b  = (const float*)d_in[13];
    const float* fc2w  = (const float*)d_in[14];
    const float* fc2b  = (const float*)d_in[15];
    float* out = (float*)d_out;

    unsigned *xn, *yn, *qb, *kvb, *ao, *xn2, *hb, *wbuf;
    float *x1, *bexp;
    cudaGetSymbolAddress((void**)&xn,  g_xn);
    cudaGetSymbolAddress((void**)&yn,  g_yn);
    cudaGetSymbolAddress((void**)&qb,  g_q);
    cudaGetSymbolAddress((void**)&kvb, g_kv);
    cudaGetSymbolAddress((void**)&ao,  g_ao);
    cudaGetSymbolAddress((void**)&x1,  g_x1);
    cudaGetSymbolAddress((void**)&xn2, g_xn2);
    cudaGetSymbolAddress((void**)&hb,  g_h);
    cudaGetSymbolAddress((void**)&bexp, g_bias);
    cudaGetSymbolAddress((void**)&wbuf, g_w);

    // 0) weight conversion (k-pair packing, [K2][N]) + bias expansion (tiny)
    cvt_all_kernel<<<(221184 + 255) / 256, 256>>>(qkvw, projw, fc1w, fc2w, wbuf);
    bias_expand_kernel<<<NHEAD, 256>>>(rpb, bexp);

    // 1) LN1 + window permutation (bf16 out)
    ln_perm_kernel<<<TOKENS / 8, 256>>>(x, y, n1g, n1b, xn, yn);

    // 2) Q = (yn @ Wq + bq) * SCALE   -> bf16, N=192 WN24
    gemm_bf16_kernel<24><<<dim3(2, TOKENS / 128), 256>>>(
        yn, wbuf + WOFF_QKV, qkvb, nullptr, qb, 192, 576, 192, QSCALE, 0);
    // 3) KV = xn @ W[k|v] + b         -> bf16, N=384 WN32 (B col offset 192 uints)
    gemm_bf16_kernel<32><<<dim3(3, TOKENS / 128), 256>>>(
        xn, wbuf + WOFF_QKV + 192, qkvb + 192, nullptr, kvb, 192, 576, 384, 1.0f, 0);
    // 4) window attention (bf16 tensor cores)
    attn_mma_kernel<<<dim3(NWIN, NHEAD), 128>>>(qb, kvb, bexp, ao);

    // 5) x1 = x + ao @ proj_w + proj_b  (un-permute) -> fp32, N=192 WN24
    gemm_bf16_kernel<24><<<dim3(2, TOKENS / 128), 256>>>(
        ao, wbuf + WOFF_PROJ, projb, x, x1, 192, 192, 192, 1.0f, 1);
    // 6) LN2 (bf16 out)
    ln_kernel<<<TOKENS / 8, 256>>>(x1, n2g, n2b, xn2);

    // 7) h = gelu(xn2 @ fc1_w + fc1_b)  -> bf16, N=768 WN32
    gemm_bf16_kernel<32><<<dim3(6, TOKENS / 128), 256>>>(
        xn2, wbuf + WOFF_FC1, fc1b, nullptr, hb, 192, 768, 768, 1.0f, 2);
    // 8) out = x1 + h @ fc2_w + fc2_b   -> fp32, N=192 WN24, K=768
    gemm_bf16_kernel<24><<<dim3(2, TOKENS / 128), 256>>>(
        hb, wbuf + WOFF_FC2, fc2b, x1, out, 768, 192, 192, 1.0f, 3);
}

// round 14
// speedup vs baseline: 1.9457x; 1.0621x over previous
#include <cuda_runtime.h>
#include <math.h>

#define TOKENS 131072
#define CEMB   192
#define NHEAD  6
#define HDIM   32
#define NWIN   2048
#define QSCALE 0.17677669529663687f  // 1/sqrt(32)

// ---------------- scratch (device globals; no runtime allocation) ----------
__device__ unsigned g_xn [(size_t)TOKENS * 96];    // LN1(x), window order, bf16
__device__ unsigned g_yn [(size_t)TOKENS * 96];    // LN1(y), window order, bf16
__device__ unsigned g_q  [(size_t)TOKENS * 96];    // scaled Q, window order, bf16
__device__ unsigned g_kv [(size_t)TOKENS * 192];   // K|V, window order, bf16
__device__ unsigned g_ao [(size_t)TOKENS * 96];    // attn out, window order, bf16
__device__ float    g_x1 [(size_t)TOKENS * CEMB];  // x + proj(attn), natural, fp32
__device__ unsigned g_xn2[(size_t)TOKENS * 96];    // LN2(x1), natural, bf16
__device__ unsigned g_h  [(size_t)TOKENS * 384];   // MLP hidden, bf16
__device__ float    g_bias[NHEAD * 64 * 64];       // expanded rel-pos bias
// weights bf16, PRE-PACKED as [K/2][N] uints: elem(k2,n) = pack(W[2k2][n], W[2k2+1][n])
__device__ unsigned g_w  [221184];                 // qkv|proj|fc1|fc2

#define WOFF_QKV  0
#define WOFF_PROJ 55296
#define WOFF_FC1  73728
#define WOFF_FC2  147456

// ---------------- helpers ---------------------------------------------------
__device__ __forceinline__ unsigned pack_bf16(float lo, float hi) {
    unsigned r;
    asm("cvt.rn.bf16x2.f32 %0, %1, %2;" : "=r"(r) : "f"(hi), "f"(lo));
    return r;
}

__device__ __forceinline__ float gelu_exact(float v) {
    return 0.5f * v * (1.0f + erff(v * 0.70710678118654752f));
}

__device__ __forceinline__ void mma_bf16(float* c, const unsigned* a, const unsigned* b) {
    asm volatile(
        "mma.sync.aligned.m16n8k16.row.col.f32.bf16.bf16.f32 "
        "{%0,%1,%2,%3}, {%4,%5,%6,%7}, {%8,%9}, {%0,%1,%2,%3};"
        : "+f"(c[0]), "+f"(c[1]), "+f"(c[2]), "+f"(c[3])
        : "r"(a[0]), "r"(a[1]), "r"(a[2]), "r"(a[3]), "r"(b[0]), "r"(b[1]));
}

__device__ __forceinline__ void ldsm_x4(unsigned* r, const unsigned* smem_ptr) {
    unsigned addr = (unsigned)__cvta_generic_to_shared(smem_ptr);
    asm volatile("ldmatrix.sync.aligned.m8n8.x4.shared.b16 {%0,%1,%2,%3}, [%4];"
                 : "=r"(r[0]), "=r"(r[1]), "=r"(r[2]), "=r"(r[3]) : "r"(addr));
}

__device__ __forceinline__ void cp16(unsigned* smem_dst, const unsigned* gsrc) {
    unsigned s = (unsigned)__cvta_generic_to_shared(smem_dst);
    asm volatile("cp.async.cg.shared.global [%0], [%1], 16;" :: "r"(s), "l"(gsrc));
}
#define CP_COMMIT() asm volatile("cp.async.commit_group;")
#define CP_WAIT0()  asm volatile("cp.async.wait_group 0;")
#define CP_WAIT1()  asm volatile("cp.async.wait_group 1;")

// ---------------- fused weight conversion (one launch) ----------------------
__global__ void cvt_all_kernel(const float* __restrict__ qkvw, const float* __restrict__ projw,
                               const float* __restrict__ fc1w, const float* __restrict__ fc2w,
                               unsigned* __restrict__ dst)
{
    int i = blockIdx.x * 256 + threadIdx.x;
    const float* src; int N, base;
    if (i < 55296)       { src = qkvw;  N = 576; base = 0; }
    else if (i < 73728)  { src = projw; N = 192; base = 55296; }
    else if (i < 147456) { src = fc1w;  N = 768; base = 73728; }
    else if (i < 221184) { src = fc2w;  N = 192; base = 147456; }
    else return;
    int j = i - base;
    int k2 = j / N, n = j % N;
    dst[i] = pack_bf16(src[(size_t)(2*k2) * N + n], src[(size_t)(2*k2+1) * N + n]);
}

// ---------------- bias table expansion --------------------------------------
__global__ void bias_expand_kernel(const float* __restrict__ rpb, float* __restrict__ bias)
{
    int head = blockIdx.x;
    for (int idx = threadIdx.x; idx < 64 * 64; idx += 256) {
        int i = idx >> 6, j = idx & 63;
        int iz = i >> 4, iy = (i >> 2) & 3, ix = i & 3;
        int jz = j >> 4, jy = (j >> 2) & 3, jx = j & 3;
        int ridx = (iz - jz + 3) * 49 + (iy - jy + 3) * 7 + (ix - jx + 3);
        bias[head * 4096 + idx] = rpb[ridx * NHEAD + head];
    }
}

// ---------------- LayerNorm (float4 in, packed bf16 out) --------------------
__device__ __forceinline__ void warp_sum2(float& s, float& ss) {
#pragma unroll
    for (int o = 16; o; o >>= 1) {
        s  += __shfl_xor_sync(0xffffffffu, s,  o);
        ss += __shfl_xor_sync(0xffffffffu, ss, o);
    }
}

__device__ __forceinline__ void ln_row_f4(
    const float4* __restrict__ in, unsigned* __restrict__ outu,
    float4 g0, float4 b0, float4 g1, float4 b1, int lane, bool hi)
{
    float4 a = in[lane];
    float4 c = hi ? in[32 + lane] : make_float4(0.f, 0.f, 0.f, 0.f);
    float s  = a.x + a.y + a.z + a.w + c.x + c.y + c.z + c.w;
    float ss = a.x*a.x + a.y*a.y + a.z*a.z + a.w*a.w
             + c.x*c.x + c.y*c.y + c.z*c.z + c.w*c.w;
    warp_sum2(s, ss);
    float mean = s * (1.f/192.f);
    float var  = ss * (1.f/192.f) - mean * mean;
    float r = rsqrtf(var + 1e-5f);
    uint2 o;
    o.x = pack_bf16((a.x - mean) * r * g0.x + b0.x, (a.y - mean) * r * g0.y + b0.y);
    o.y = pack_bf16((a.z - mean) * r * g0.z + b0.z, (a.w - mean) * r * g0.w + b0.w);
    *(uint2*)&outu[lane * 2] = o;
    if (hi) {
        uint2 p;
        p.x = pack_bf16((c.x - mean) * r * g1.x + b1.x, (c.y - mean) * r * g1.y + b1.y);
        p.y = pack_bf16((c.z - mean) * r * g1.z + b1.z, (c.w - mean) * r * g1.w + b1.w);
        *(uint2*)&outu[64 + lane * 2] = p;
    }
}

__global__ void __launch_bounds__(256) ln_perm_kernel(
    const float* __restrict__ x, const float* __restrict__ y,
    const float* __restrict__ g, const float* __restrict__ b,
    unsigned* __restrict__ xn, unsigned* __restrict__ yn)
{
    int token = blockIdx.x * 8 + (threadIdx.x >> 5);
    int lane  = threadIdx.x & 31;
    bool hi = lane < 16;
    int w = token & 63, h = (token >> 6) & 63, d = token >> 12;
    int win  = (((d >> 2) << 4) + (h >> 2)) * 16 + (w >> 2);
    int pos  = ((d & 3) << 4) + ((h & 3) << 2) + (w & 3);
    size_t prow = (size_t)win * 64 + pos;

    const float4* g4 = (const float4*)g;
    const float4* b4 = (const float4*)b;
    float4 g0 = g4[lane], b0 = b4[lane];
    float4 g1 = make_float4(0,0,0,0), b1 = g1;
    if (hi) { g1 = g4[32 + lane]; b1 = b4[32 + lane]; }

    ln_row_f4((const float4*)(x + (size_t)token * CEMB), xn + prow * 96,
              g0, b0, g1, b1, lane, hi);
    ln_row_f4((const float4*)(y + (size_t)token * CEMB), yn + prow * 96,
              g0, b0, g1, b1, lane, hi);
}

__global__ void __launch_bounds__(256) ln_kernel(
    const float* __restrict__ x, const float* __restrict__ g, const float* __restrict__ b,
    unsigned* __restrict__ xn)
{
    int token = blockIdx.x * 8 + (threadIdx.x >> 5);
    int lane  = threadIdx.x & 31;
    bool hi = lane < 16;
    const float4* g4 = (const float4*)g;
    const float4* b4 = (const float4*)b;
    float4 g0 = g4[lane], b0 = b4[lane];
    float4 g1 = make_float4(0,0,0,0), b1 = g1;
    if (hi) { g1 = g4[32 + lane]; b1 = b4[32 + lane]; }
    ln_row_f4((const float4*)(x + (size_t)token * CEMB), xn + (size_t)token * 96,
              g0, b0, g1, b1, lane, hi);
}

// ---------------- bf16 GEMM, 3-stage cp.async pipeline + LDSM ---------------
// A: bf16 packed [M, K/2] uints. B: bf16 PRE-PACKED [K/2, N] uints (k-pairs).
// CTA tile 128 x (4*WN); 256 threads = 8 warps (2x4), warp 64 x WN.
// mode 0: bf16 C=(acc+bias)*scale; 1: f32 C[perm]=..+resid; 2: bf16 gelu; 3: f32 +resid
template<int WN, int MINB>
__global__ void __launch_bounds__(256, MINB) gemm_bf16_kernel(
    const unsigned* __restrict__ Au, const unsigned* __restrict__ Bu,
    const float* __restrict__ bias, const float* __restrict__ resid,
    void* __restrict__ Cout,
    int K, int ldb2, int ldc, float scale, int mode)
{
    constexpr int BN  = WN * 4;
    constexpr int LDB = BN + 8;         // uints; ≡8 mod 32 -> conflict-free frag reads
    constexpr int NF  = WN / 8;
    constexpr int NBC = 16 * (BN / 4);  // B 16-byte chunks per tile
    constexpr int ASZ = 128 * 20;
    constexpr int BSZ = 16 * LDB;
    constexpr int STG = ASZ + BSZ;

    extern __shared__ unsigned smem[];  // 3 stages of [As | Bs]

    int tid = threadIdx.x;
    int wid = tid >> 5, lane = tid & 31;
    int g = lane >> 2, t = lane & 3;
    int wm = (wid >> 2) * 64;
    int wn = (wid & 3) * WN;
    size_t rowBase = (size_t)blockIdx.y * 128;
    int nb = blockIdx.x * BN;
    int K2 = K >> 1;

    int arow = (lane & 7) + ((lane >> 3) & 1) * 8;   // ldmatrix lane addressing
    int acol = ((lane >> 4) & 1) * 4;

    int ar[2], ac4[2];
#pragma unroll
    for (int it = 0; it < 2; it++) { int idx = tid + 256*it; ar[it] = idx >> 2; ac4[it] = (idx & 3) * 4; }
    const unsigned* Abase = Au + rowBase * K2;
    const unsigned* Bbase = Bu + nb;

    int NIT = K >> 5;

    auto stage_in = [&](int tile, int s) {
        unsigned* As = smem + s * STG;
        unsigned* Bsp = As + ASZ;
        int kn2 = tile * 16;
#pragma unroll
        for (int it = 0; it < 2; it++)
            cp16(&As[ar[it]*20 + ac4[it]], Abase + (size_t)ar[it] * K2 + kn2 + ac4[it]);
        for (int t2 = tid; t2 < NBC; t2 += 256) {
            int br = t2 / (BN/4), bc = (t2 % (BN/4)) * 4;
            cp16(&Bsp[br*LDB + bc], Bbase + (size_t)(kn2 + br) * ldb2 + bc);
        }
    };

    // prologue: stage tiles 0 and 1
    stage_in(0, 0); CP_COMMIT();
    stage_in(1, 1); CP_COMMIT();

    float acc[4][NF][4] = {};

    for (int i = 0; i < NIT; i++) {
        if (i + 1 < NIT) { CP_WAIT1(); } else { CP_WAIT0(); }
        __syncthreads();

        int buf = i % 3;
        unsigned* Asb = smem + buf * STG;
        unsigned* Bsb = Asb + ASZ;

#pragma unroll
        for (int ks = 0; ks < 2; ks++) {
            int kp = ks * 8;
            unsigned bf[NF][2];
#pragma unroll
            for (int nf = 0; nf < NF; nf++) {
                bf[nf][0] = Bsb[(kp + t    )*LDB + wn + nf*8 + g];
                bf[nf][1] = Bsb[(kp + t + 4)*LDB + wn + nf*8 + g];
            }
#pragma unroll
            for (int mf = 0; mf < 4; mf++) {
                unsigned af[4];
                ldsm_x4(af, &Asb[(wm + mf*16 + arow)*20 + kp + acol]);
#pragma unroll
                for (int nf = 0; nf < NF; nf++) mma_bf16(acc[mf][nf], af, bf[nf]);
            }
        }

        if (i + 2 < NIT) {
            stage_in(i + 2, (i + 2) % 3);
            CP_COMMIT();
        }
    }

#pragma unroll
    for (int mf = 0; mf < 4; mf++) {
#pragma unroll
        for (int half = 0; half < 2; half++) {
            size_t row = rowBase + wm + mf*16 + g + half*8;
            size_t orow = row;
            if (mode == 1) {
                int win = (int)(row >> 6), pos = (int)(row & 63);
                int wd = win >> 8, wh = (win >> 4) & 15, ww = win & 15;
                int d = (wd << 2) + (pos >> 4);
                int h = (wh << 2) + ((pos >> 2) & 3);
                int w = (ww << 2) + (pos & 3);
                orow = ((size_t)(d * 64 + h)) * 64 + w;
            }
#pragma unroll
            for (int nf = 0; nf < NF; nf++) {
                int col = nb + wn + nf*8 + 2*t;
                float v0 = acc[mf][nf][half*2+0] + bias[col];
                float v1 = acc[mf][nf][half*2+1] + bias[col+1];
                if (mode == 0) {
                    ((unsigned*)Cout)[(orow * (size_t)ldc + col) >> 1] =
                        pack_bf16(v0 * scale, v1 * scale);
                } else if (mode == 2) {
                    ((unsigned*)Cout)[(orow * (size_t)ldc + col) >> 1] =
                        pack_bf16(gelu_exact(v0), gelu_exact(v1));
                } else {
                    const float* rs = resid + (mode == 1 ? orow : row) * CEMB + col;
                    float2 o = make_float2(v0 + rs[0], v1 + rs[1]);
                    *(float2*)((float*)Cout + orow * (size_t)ldc + col) = o;
                }
            }
        }
    }
}

// ---------------- bf16 tensor-core windowed cross-attention -----------------
// one block per (window, head); 128 threads (4 warps, 16 rows each). bf16 I/O.
__global__ void __launch_bounds__(128) attn_mma_kernel(
    const unsigned* __restrict__ qu, const unsigned* __restrict__ kvu,
    const float* __restrict__ bias, unsigned* __restrict__ outu)
{
    __shared__ unsigned sm_a[64 * 20 * 2];   // Qs | Ks; reused as Ps[64][36]
    __shared__ unsigned sm_v[32 * 40];

    unsigned (*Qs)[20] = (unsigned(*)[20])sm_a;
    unsigned (*Ks)[20] = (unsigned(*)[20])(sm_a + 64*20);
    unsigned (*Ps)[36] = (unsigned(*)[36])sm_a;   // 64*36 = 2304 <= 2560
    unsigned (*Vs)[40] = (unsigned(*)[40])sm_v;   // [j2][d], pairs along j

    int win = blockIdx.x, head = blockIdx.y;
    int tid = threadIdx.x;
    int wid = tid >> 5, lane = tid & 31;
    int g = lane >> 2, t = lane & 3;
    int arow = (lane & 7) + ((lane >> 3) & 1) * 8;
    int acol = ((lane >> 4) & 1) * 4;

    const unsigned* qb = qu  + (size_t)win * 64 * 96  + head * 16;
    const unsigned* kb = kvu + (size_t)win * 64 * 192 + head * 16;
    const unsigned* vb = kb + 96;

    for (int idx = tid; idx < 64 * 8; idx += 128) {
        int r = idx >> 3, u2 = (idx & 7) * 2;
        *(uint2*)&Qs[r][u2] = *(const uint2*)(qb + (size_t)r * 96  + u2);
        *(uint2*)&Ks[r][u2] = *(const uint2*)(kb + (size_t)r * 192 + u2);
    }
    for (int idx = tid; idx < 32 * 16; idx += 128) {
        int j2 = idx >> 4, c2 = idx & 15;
        unsigned ue = vb[(size_t)(2*j2    ) * 192 + c2];
        unsigned uo = vb[(size_t)(2*j2 + 1) * 192 + c2];
        Vs[j2][2*c2    ] = __byte_perm(ue, uo, 0x5410);
        Vs[j2][2*c2 + 1] = __byte_perm(ue, uo, 0x7632);
    }
    __syncthreads();

    // ---- S = Q K^T (64x64x32, bf16) ----
    int r0 = wid * 16;
    float sacc[8][4] = {};
#pragma unroll
    for (int ks = 0; ks < 2; ks++) {
        int kp = ks * 8;
        unsigned af[4];
        ldsm_x4(af, &Qs[r0 + arow][kp + acol]);
#pragma unroll
        for (int nt = 0; nt < 8; nt++) {
            unsigned bf[2];
            bf[0] = Ks[nt*8 + g][kp + t];
            bf[1] = Ks[nt*8 + g][kp + t + 4];
            mma_bf16(sacc[nt], af, bf);
        }
    }
    __syncthreads();   // all warps done with Qs/Ks before Ps overwrites

    // ---- bias + softmax (rows rA, rB) ----
    int rA = r0 + g, rB = rA + 8;
    const float* bA = bias + head * 4096 + rA * 64;
    const float* bB = bias + head * 4096 + rB * 64;

    float vA[16], vB[16];
    float mA = -1e30f, mB = -1e30f;
#pragma unroll
    for (int nt = 0; nt < 8; nt++) {
#pragma unroll
        for (int e = 0; e < 2; e++) {
            int j = nt*8 + 2*t + e;
            float a = sacc[nt][e]     + bA[j];
            float b = sacc[nt][2 + e] + bB[j];
            vA[nt*2+e] = a; mA = fmaxf(mA, a);
            vB[nt*2+e] = b; mB = fmaxf(mB, b);
        }
    }
    mA = fmaxf(mA, __shfl_xor_sync(0xffffffffu, mA, 1));
    mA = fmaxf(mA, __shfl_xor_sync(0xffffffffu, mA, 2));
    mB = fmaxf(mB, __shfl_xor_sync(0xffffffffu, mB, 1));
    mB = fmaxf(mB, __shfl_xor_sync(0xffffffffu, mB, 2));

    float sA = 0.f, sB = 0.f;
#pragma unroll
    for (int i = 0; i < 16; i++) {
        vA[i] = __expf(vA[i] - mA); sA += vA[i];
        vB[i] = __expf(vB[i] - mB); sB += vB[i];
    }
    sA += __shfl_xor_sync(0xffffffffu, sA, 1);
    sA += __shfl_xor_sync(0xffffffffu, sA, 2);
    sB += __shfl_xor_sync(0xffffffffu, sB, 1);
    sB += __shfl_xor_sync(0xffffffffu, sB, 2);
    float rAi = 1.f / sA, rBi = 1.f / sB;

#pragma unroll
    for (int nt = 0; nt < 8; nt++) {
        Ps[rA][nt*4 + t] = pack_bf16(vA[nt*2] * rAi, vA[nt*2+1] * rAi);
        Ps[rB][nt*4 + t] = pack_bf16(vB[nt*2] * rBi, vB[nt*2+1] * rBi);
    }
    __syncwarp();   // each warp reads only its own 16 Ps rows

    // ---- O = P V (64x32x64, bf16) ----
    float oacc[4][4] = {};
#pragma unroll
    for (int ks = 0; ks < 4; ks++) {
        int kp = ks * 8;
        unsigned af[4];
        ldsm_x4(af, &Ps[r0 + arow][kp + acol]);
#pragma unroll
        for (int nt = 0; nt < 4; nt++) {
            unsigned bf[2];
            bf[0] = Vs[kp + t    ][nt*8 + g];
            bf[1] = Vs[kp + t + 4][nt*8 + g];
            mma_bf16(oacc[nt], af, bf);
        }
    }

    unsigned* ob = outu + (size_t)win * 64 * 96 + head * 16;
#pragma unroll
    for (int nt = 0; nt < 4; nt++) {
        int c2 = nt*4 + t;
        ob[(size_t)rA * 96 + c2] = pack_bf16(oacc[nt][0], oacc[nt][1]);
        ob[(size_t)rB * 96 + c2] = pack_bf16(oacc[nt][2], oacc[nt][3]);
    }
}

// ---------------- launch ----------------------------------------------------
extern "C" void kernel_launch(void* const* d_in, const int* in_sizes, int n_in,
                              void* d_out, int out_size)
{
    const float* x     = (const float*)d_in[0];
    const float* y     = (const float*)d_in[1];
    const float* n1g   = (const float*)d_in[3];
    const float* n1b   = (const float*)d_in[4];
    const float* qkvw  = (const float*)d_in[5];
    const float* qkvb  = (const float*)d_in[6];
    const float* rpb   = (const float*)d_in[7];
    const float* projw = (const float*)d_in[8];
    const float* projb = (const float*)d_in[9];
    const float* n2g   = (const float*)d_in[10];
    const float* n2b   = (const float*)d_in[11];
    const float* fc1w  = (const float*)d_in[12];
    const float* fc1b  = (const float*)d_in[13];
    const float* fc2w  = (const float*)d_in[14];
    const float* fc2b  = (const float*)d_in[15];
    float* out = (float*)d_out;

    unsigned *xn, *yn, *qb, *kvb, *ao, *xn2, *hb, *wbuf;
    float *x1, *bexp;
    cudaGetSymbolAddress((void**)&xn,  g_xn);
    cudaGetSymbolAddress((void**)&yn,  g_yn);
    cudaGetSymbolAddress((void**)&qb,  g_q);
    cudaGetSymbolAddress((void**)&kvb, g_kv);
    cudaGetSymbolAddress((void**)&ao,  g_ao);
    cudaGetSymbolAddress((void**)&x1,  g_x1);
    cudaGetSymbolAddress((void**)&xn2, g_xn2);
    cudaGetSymbolAddress((void**)&hb,  g_h);
    cudaGetSymbolAddress((void**)&bexp, g_bias);
    cudaGetSymbolAddress((void**)&wbuf, g_w);

    // dynamic smem sizes: 3 stages of (As + Bs)
    const int smem24 = 3 * (128*20 + 16*(24*4 + 8)) * 4;   // 50688 B
    const int smem32 = 3 * (128*20 + 16*(32*4 + 8)) * 4;   // 56832 B
    cudaFuncSetAttribute(gemm_bf16_kernel<24,3>,
                         cudaFuncAttributeMaxDynamicSharedMemorySize, smem24);
    cudaFuncSetAttribute(gemm_bf16_kernel<32,2>,
                         cudaFuncAttributeMaxDynamicSharedMemorySize, smem32);

    // 0) weight conversion (k-pair packing, [K2][N]) + bias expansion (tiny)
    cvt_all_kernel<<<(221184 + 255) / 256, 256>>>(qkvw, projw, fc1w, fc2w, wbuf);
    bias_expand_kernel<<<NHEAD, 256>>>(rpb, bexp);

    // 1) LN1 + window permutation (bf16 out)
    ln_perm_kernel<<<TOKENS / 8, 256>>>(x, y, n1g, n1b, xn, yn);

    // 2) Q = (yn @ Wq + bq) * SCALE   -> bf16, N=192 WN24
    gemm_bf16_kernel<24,3><<<dim3(2, TOKENS / 128), 256, smem24>>>(
        yn, wbuf + WOFF_QKV, qkvb, nullptr, qb, 192, 576, 192, QSCALE, 0);
    // 3) KV = xn @ W[k|v] + b         -> bf16, N=384 WN32 (B col offset 192 uints)
    gemm_bf16_kernel<32,2><<<dim3(3, TOKENS / 128), 256, smem32>>>(
        xn, wbuf + WOFF_QKV + 192, qkvb + 192, nullptr, kvb, 192, 576, 384, 1.0f, 0);
    // 4) window attention (bf16 tensor cores)
    attn_mma_kernel<<<dim3(NWIN, NHEAD), 128>>>(qb, kvb, bexp, ao);

    // 5) x1 = x + ao @ proj_w + proj_b  (un-permute) -> fp32, N=192 WN24
    gemm_bf16_kernel<24,3><<<dim3(2, TOKENS / 128), 256, smem24>>>(
        ao, wbuf + WOFF_PROJ, projb, x, x1, 192, 192, 192, 1.0f, 1);
    // 6) LN2 (bf16 out)
    ln_kernel<<<TOKENS / 8, 256>>>(x1, n2g, n2b, xn2);

    // 7) h = gelu(xn2 @ fc1_w + fc1_b)  -> bf16, N=768 WN32
    gemm_bf16_kernel<32,2><<<dim3(6, TOKENS / 128), 256, smem32>>>(
        xn2, wbuf + WOFF_FC1, fc1b, nullptr, hb, 192, 768, 768, 1.0f, 2);
    // 8) out = x1 + h @ fc2_w + fc2_b   -> fp32, N=192 WN24, K=768
    gemm_bf16_kernel<24,3><<<dim3(2, TOKENS / 128), 256, smem24>>>(
        hb, wbuf + WOFF_FC2, fc2b, x1, out, 768, 192, 192, 1.0f, 3);
}

// round 16
// speedup vs baseline: 1.9677x; 1.0113x over previous
#include <cuda_runtime.h>
#include <math.h>

#define TOKENS 131072
#define CEMB   192
#define NHEAD  6
#define HDIM   32
#define NWIN   2048
#define QSCALE 0.17677669529663687f  // 1/sqrt(32)

// ---------------- scratch (device globals; no runtime allocation) ----------
__device__ unsigned g_xn [(size_t)TOKENS * 96];    // LN1(x), window order, bf16
__device__ unsigned g_yn [(size_t)TOKENS * 96];    // LN1(y), window order, bf16
__device__ unsigned g_q  [(size_t)TOKENS * 96];    // scaled Q, window order, bf16
__device__ unsigned g_kv [(size_t)TOKENS * 192];   // K|V, window order, bf16
__device__ unsigned g_ao [(size_t)TOKENS * 96];    // attn out, window order, bf16
__device__ float    g_x1 [(size_t)TOKENS * CEMB];  // x + proj(attn), natural, fp32
__device__ unsigned g_xn2[(size_t)TOKENS * 96];    // LN2(x1), natural, bf16
__device__ unsigned g_h  [(size_t)TOKENS * 384];   // MLP hidden, bf16
__device__ float    g_bias[NHEAD * 64 * 64];       // expanded rel-pos bias
// weights bf16, PRE-PACKED as [K/2][N] uints: elem(k2,n) = pack(W[2k2][n], W[2k2+1][n])
__device__ unsigned g_w  [221184];                 // qkv|proj|fc1|fc2

#define WOFF_QKV  0
#define WOFF_PROJ 55296
#define WOFF_FC1  73728
#define WOFF_FC2  147456

// ---------------- helpers ---------------------------------------------------
__device__ __forceinline__ unsigned pack_bf16(float lo, float hi) {
    unsigned r;
    asm("cvt.rn.bf16x2.f32 %0, %1, %2;" : "=r"(r) : "f"(hi), "f"(lo));
    return r;
}

__device__ __forceinline__ float gelu_exact(float v) {
    return 0.5f * v * (1.0f + erff(v * 0.70710678118654752f));
}

__device__ __forceinline__ void mma_bf16(float* c, const unsigned* a, const unsigned* b) {
    asm volatile(
        "mma.sync.aligned.m16n8k16.row.col.f32.bf16.bf16.f32 "
        "{%0,%1,%2,%3}, {%4,%5,%6,%7}, {%8,%9}, {%0,%1,%2,%3};"
        : "+f"(c[0]), "+f"(c[1]), "+f"(c[2]), "+f"(c[3])
        : "r"(a[0]), "r"(a[1]), "r"(a[2]), "r"(a[3]), "r"(b[0]), "r"(b[1]));
}

__device__ __forceinline__ void ldsm_x4(unsigned* r, const unsigned* smem_ptr) {
    unsigned addr = (unsigned)__cvta_generic_to_shared(smem_ptr);
    asm volatile("ldmatrix.sync.aligned.m8n8.x4.shared.b16 {%0,%1,%2,%3}, [%4];"
                 : "=r"(r[0]), "=r"(r[1]), "=r"(r[2]), "=r"(r[3]) : "r"(addr));
}

__device__ __forceinline__ void cp16(unsigned* smem_dst, const unsigned* gsrc) {
    unsigned s = (unsigned)__cvta_generic_to_shared(smem_dst);
    asm volatile("cp.async.cg.shared.global [%0], [%1], 16;" :: "r"(s), "l"(gsrc));
}
#define CP_COMMIT() asm volatile("cp.async.commit_group;")
#define CP_WAIT0()  asm volatile("cp.async.wait_group 0;")
#define CP_WAIT1()  asm volatile("cp.async.wait_group 1;")

// ---------------- fused weight conversion (one launch) ----------------------
__global__ void cvt_all_kernel(const float* __restrict__ qkvw, const float* __restrict__ projw,
                               const float* __restrict__ fc1w, const float* __restrict__ fc2w,
                               unsigned* __restrict__ dst)
{
    int i = blockIdx.x * 256 + threadIdx.x;
    const float* src; int N, base;
    if (i < 55296)       { src = qkvw;  N = 576; base = 0; }
    else if (i < 73728)  { src = projw; N = 192; base = 55296; }
    else if (i < 147456) { src = fc1w;  N = 768; base = 73728; }
    else if (i < 221184) { src = fc2w;  N = 192; base = 147456; }
    else return;
    int j = i - base;
    int k2 = j / N, n = j % N;
    dst[i] = pack_bf16(src[(size_t)(2*k2) * N + n], src[(size_t)(2*k2+1) * N + n]);
}

// ---------------- bias table expansion --------------------------------------
__global__ void bias_expand_kernel(const float* __restrict__ rpb, float* __restrict__ bias)
{
    int head = blockIdx.x;
    for (int idx = threadIdx.x; idx < 64 * 64; idx += 256) {
        int i = idx >> 6, j = idx & 63;
        int iz = i >> 4, iy = (i >> 2) & 3, ix = i & 3;
        int jz = j >> 4, jy = (j >> 2) & 3, jx = j & 3;
        int ridx = (iz - jz + 3) * 49 + (iy - jy + 3) * 7 + (ix - jx + 3);
        bias[head * 4096 + idx] = rpb[ridx * NHEAD + head];
    }
}

// ---------------- LayerNorm (float4 in, packed bf16 out) --------------------
__device__ __forceinline__ void warp_sum2(float& s, float& ss) {
#pragma unroll
    for (int o = 16; o; o >>= 1) {
        s  += __shfl_xor_sync(0xffffffffu, s,  o);
        ss += __shfl_xor_sync(0xffffffffu, ss, o);
    }
}

__device__ __forceinline__ void ln_row_f4(
    const float4* __restrict__ in, unsigned* __restrict__ outu,
    float4 g0, float4 b0, float4 g1, float4 b1, int lane, bool hi)
{
    float4 a = in[lane];
    float4 c = hi ? in[32 + lane] : make_float4(0.f, 0.f, 0.f, 0.f);
    float s  = a.x + a.y + a.z + a.w + c.x + c.y + c.z + c.w;
    float ss = a.x*a.x + a.y*a.y + a.z*a.z + a.w*a.w
             + c.x*c.x + c.y*c.y + c.z*c.z + c.w*c.w;
    warp_sum2(s, ss);
    float mean = s * (1.f/192.f);
    float var  = ss * (1.f/192.f) - mean * mean;
    float r = rsqrtf(var + 1e-5f);
    uint2 o;
    o.x = pack_bf16((a.x - mean) * r * g0.x + b0.x, (a.y - mean) * r * g0.y + b0.y);
    o.y = pack_bf16((a.z - mean) * r * g0.z + b0.z, (a.w - mean) * r * g0.w + b0.w);
    *(uint2*)&outu[lane * 2] = o;
    if (hi) {
        uint2 p;
        p.x = pack_bf16((c.x - mean) * r * g1.x + b1.x, (c.y - mean) * r * g1.y + b1.y);
        p.y = pack_bf16((c.z - mean) * r * g1.z + b1.z, (c.w - mean) * r * g1.w + b1.w);
        *(uint2*)&outu[64 + lane * 2] = p;
    }
}

__global__ void __launch_bounds__(256) ln_perm_kernel(
    const float* __restrict__ x, const float* __restrict__ y,
    const float* __restrict__ g, const float* __restrict__ b,
    unsigned* __restrict__ xn, unsigned* __restrict__ yn)
{
    int token = blockIdx.x * 8 + (threadIdx.x >> 5);
    int lane  = threadIdx.x & 31;
    bool hi = lane < 16;
    int w = token & 63, h = (token >> 6) & 63, d = token >> 12;
    int win  = (((d >> 2) << 4) + (h >> 2)) * 16 + (w >> 2);
    int pos  = ((d & 3) << 4) + ((h & 3) << 2) + (w & 3);
    size_t prow = (size_t)win * 64 + pos;

    const float4* g4 = (const float4*)g;
    const float4* b4 = (const float4*)b;
    float4 g0 = g4[lane], b0 = b4[lane];
    float4 g1 = make_float4(0,0,0,0), b1 = g1;
    if (hi) { g1 = g4[32 + lane]; b1 = b4[32 + lane]; }

    ln_row_f4((const float4*)(x + (size_t)token * CEMB), xn + prow * 96,
              g0, b0, g1, b1, lane, hi);
    ln_row_f4((const float4*)(y + (size_t)token * CEMB), yn + prow * 96,
              g0, b0, g1, b1, lane, hi);
}

__global__ void __launch_bounds__(256) ln_kernel(
    const float* __restrict__ x, const float* __restrict__ g, const float* __restrict__ b,
    unsigned* __restrict__ xn)
{
    int token = blockIdx.x * 8 + (threadIdx.x >> 5);
    int lane  = threadIdx.x & 31;
    bool hi = lane < 16;
    const float4* g4 = (const float4*)g;
    const float4* b4 = (const float4*)b;
    float4 g0 = g4[lane], b0 = b4[lane];
    float4 g1 = make_float4(0,0,0,0), b1 = g1;
    if (hi) { g1 = g4[32 + lane]; b1 = b4[32 + lane]; }
    ln_row_f4((const float4*)(x + (size_t)token * CEMB), xn + (size_t)token * 96,
              g0, b0, g1, b1, lane, hi);
}

// ---------------- bf16 GEMM, 3-stage cp.async pipeline + LDSM ---------------
// Mainloop unrolled by 3: compile-time buffer indices (NIT % 3 == 0 for K=192/768).
// A: bf16 packed [M, K/2] uints. B: bf16 PRE-PACKED [K/2, N] uints (k-pairs).
// CTA tile 128 x (4*WN); 256 threads = 8 warps (2x4), warp 64 x WN.
// mode 0: bf16 C=(acc+bias)*scale; 1: f32 C[perm]=..+resid; 2: bf16 gelu; 3: f32 +resid
template<int WN, int MINB>
__global__ void __launch_bounds__(256, MINB) gemm_bf16_kernel(
    const unsigned* __restrict__ Au, const unsigned* __restrict__ Bu,
    const float* __restrict__ bias, const float* __restrict__ resid,
    void* __restrict__ Cout,
    int K, int ldb2, int ldc, float scale, int mode)
{
    constexpr int BN  = WN * 4;
    constexpr int LDB = BN + 8;         // uints; ≡8 mod 32 -> conflict-free frag reads
    constexpr int NF  = WN / 8;
    constexpr int NBC = 16 * (BN / 4);  // B 16-byte chunks per tile
    constexpr int ASZ = 128 * 20;
    constexpr int BSZ = 16 * LDB;
    constexpr int STG = ASZ + BSZ;

    extern __shared__ unsigned smem[];  // 3 stages of [As | Bs]

    int tid = threadIdx.x;
    int wid = tid >> 5, lane = tid & 31;
    int g = lane >> 2, t = lane & 3;
    int wm = (wid >> 2) * 64;
    int wn = (wid & 3) * WN;
    size_t rowBase = (size_t)blockIdx.y * 128;
    int nb = blockIdx.x * BN;
    int K2 = K >> 1;

    int arow = (lane & 7) + ((lane >> 3) & 1) * 8;   // ldmatrix lane addressing
    int acol = ((lane >> 4) & 1) * 4;

    int ar[2], ac4[2];
#pragma unroll
    for (int it = 0; it < 2; it++) { int idx = tid + 256*it; ar[it] = idx >> 2; ac4[it] = (idx & 3) * 4; }
    const unsigned* Abase = Au + rowBase * K2;
    const unsigned* Bbase = Bu + nb;

    int NIT = K >> 5;   // divisible by 3 (6 or 24)

    auto stage_in = [&](int tile, unsigned* As) {
        unsigned* Bsp = As + ASZ;
        int kn2 = tile * 16;
#pragma unroll
        for (int it = 0; it < 2; it++)
            cp16(&As[ar[it]*20 + ac4[it]], Abase + (size_t)ar[it] * K2 + kn2 + ac4[it]);
        for (int t2 = tid; t2 < NBC; t2 += 256) {
            int br = t2 / (BN/4), bc = (t2 % (BN/4)) * 4;
            cp16(&Bsp[br*LDB + bc], Bbase + (size_t)(kn2 + br) * ldb2 + bc);
        }
    };

    auto compute = [&](const unsigned* Asb, float (*acc)[NF][4]) {
        const unsigned* Bsb = Asb + ASZ;
#pragma unroll
        for (int ks = 0; ks < 2; ks++) {
            int kp = ks * 8;
            unsigned bf[NF][2];
#pragma unroll
            for (int nf = 0; nf < NF; nf++) {
                bf[nf][0] = Bsb[(kp + t    )*LDB + wn + nf*8 + g];
                bf[nf][1] = Bsb[(kp + t + 4)*LDB + wn + nf*8 + g];
            }
#pragma unroll
            for (int mf = 0; mf < 4; mf++) {
                unsigned af[4];
                ldsm_x4(af, &Asb[(wm + mf*16 + arow)*20 + kp + acol]);
#pragma unroll
                for (int nf = 0; nf < NF; nf++) mma_bf16(acc[mf][nf], af, bf[nf]);
            }
        }
    };

    // prologue: stage tiles 0 and 1
    stage_in(0, smem); CP_COMMIT();
    stage_in(1, smem + STG); CP_COMMIT();

    float acc[4][NF][4] = {};

    for (int i0 = 0; i0 < NIT; i0 += 3) {
#pragma unroll
        for (int s = 0; s < 3; s++) {
            int i = i0 + s;
            if (i + 1 < NIT) { CP_WAIT1(); } else { CP_WAIT0(); }
            __syncthreads();
            compute(smem + s * STG, acc);   // compile-time stage base
            if (i + 2 < NIT) {
                stage_in(i + 2, smem + ((s + 2) % 3) * STG);   // compile-time
                CP_COMMIT();
            }
        }
    }

#pragma unroll
    for (int mf = 0; mf < 4; mf++) {
#pragma unroll
        for (int half = 0; half < 2; half++) {
            size_t row = rowBase + wm + mf*16 + g + half*8;
            size_t orow = row;
            if (mode == 1) {
                int win = (int)(row >> 6), pos = (int)(row & 63);
                int wd = win >> 8, wh = (win >> 4) & 15, ww = win & 15;
                int d = (wd << 2) + (pos >> 4);
                int h = (wh << 2) + ((pos >> 2) & 3);
                int w = (ww << 2) + (pos & 3);
                orow = ((size_t)(d * 64 + h)) * 64 + w;
            }
#pragma unroll
            for (int nf = 0; nf < NF; nf++) {
                int col = nb + wn + nf*8 + 2*t;
                float2 bb = *(const float2*)(bias + col);
                float v0 = acc[mf][nf][half*2+0] + bb.x;
                float v1 = acc[mf][nf][half*2+1] + bb.y;
                if (mode == 0) {
                    ((unsigned*)Cout)[(orow * (size_t)ldc + col) >> 1] =
                        pack_bf16(v0 * scale, v1 * scale);
                } else if (mode == 2) {
                    ((unsigned*)Cout)[(orow * (size_t)ldc + col) >> 1] =
                        pack_bf16(gelu_exact(v0), gelu_exact(v1));
                } else {
                    float2 rs = *(const float2*)(resid + (mode == 1 ? orow : row) * CEMB + col);
                    float2 o = make_float2(v0 + rs.x, v1 + rs.y);
                    *(float2*)((float*)Cout + orow * (size_t)ldc + col) = o;
                }
            }
        }
    }
}

// ---------------- bf16 tensor-core windowed cross-attention -----------------
// one block per (window, head); 128 threads (4 warps, 16 rows each). bf16 I/O.
__global__ void __launch_bounds__(128) attn_mma_kernel(
    const unsigned* __restrict__ qu, const unsigned* __restrict__ kvu,
    const float* __restrict__ bias, unsigned* __restrict__ outu)
{
    __shared__ unsigned sm_a[64 * 20 * 2];   // Qs | Ks; reused as Ps[64][36]
    __shared__ unsigned sm_v[32 * 40];

    unsigned (*Qs)[20] = (unsigned(*)[20])sm_a;
    unsigned (*Ks)[20] = (unsigned(*)[20])(sm_a + 64*20);
    unsigned (*Ps)[36] = (unsigned(*)[36])sm_a;   // 64*36 = 2304 <= 2560
    unsigned (*Vs)[40] = (unsigned(*)[40])sm_v;   // [j2][d], pairs along j

    int win = blockIdx.x, head = blockIdx.y;
    int tid = threadIdx.x;
    int wid = tid >> 5, lane = tid & 31;
    int g = lane >> 2, t = lane & 3;
    int arow = (lane & 7) + ((lane >> 3) & 1) * 8;
    int acol = ((lane >> 4) & 1) * 4;

    const unsigned* qb = qu  + (size_t)win * 64 * 96  + head * 16;
    const unsigned* kb = kvu + (size_t)win * 64 * 192 + head * 16;
    const unsigned* vb = kb + 96;

    for (int idx = tid; idx < 64 * 8; idx += 128) {
        int r = idx >> 3, u2 = (idx & 7) * 2;
        *(uint2*)&Qs[r][u2] = *(const uint2*)(qb + (size_t)r * 96  + u2);
        *(uint2*)&Ks[r][u2] = *(const uint2*)(kb + (size_t)r * 192 + u2);
    }
    for (int idx = tid; idx < 32 * 16; idx += 128) {
        int j2 = idx >> 4, c2 = idx & 15;
        unsigned ue = vb[(size_t)(2*j2    ) * 192 + c2];
        unsigned uo = vb[(size_t)(2*j2 + 1) * 192 + c2];
        Vs[j2][2*c2    ] = __byte_perm(ue, uo, 0x5410);
        Vs[j2][2*c2 + 1] = __byte_perm(ue, uo, 0x7632);
    }
    __syncthreads();

    // ---- S = Q K^T (64x64x32, bf16) ----
    int r0 = wid * 16;
    float sacc[8][4] = {};
#pragma unroll
    for (int ks = 0; ks < 2; ks++) {
        int kp = ks * 8;
        unsigned af[4];
        ldsm_x4(af, &Qs[r0 + arow][kp + acol]);
#pragma unroll
        for (int nt = 0; nt < 8; nt++) {
            unsigned bf[2];
            bf[0] = Ks[nt*8 + g][kp + t];
            bf[1] = Ks[nt*8 + g][kp + t + 4];
            mma_bf16(sacc[nt], af, bf);
        }
    }
    __syncthreads();   // all warps done with Qs/Ks before Ps overwrites

    // ---- bias + softmax (rows rA, rB) ----
    int rA = r0 + g, rB = rA + 8;
    const float* bA = bias + head * 4096 + rA * 64;
    const float* bB = bias + head * 4096 + rB * 64;

    float vA[16], vB[16];
    float mA = -1e30f, mB = -1e30f;
#pragma unroll
    for (int nt = 0; nt < 8; nt++) {
#pragma unroll
        for (int e = 0; e < 2; e++) {
            int j = nt*8 + 2*t + e;
            float a = sacc[nt][e]     + bA[j];
            float b = sacc[nt][2 + e] + bB[j];
            vA[nt*2+e] = a; mA = fmaxf(mA, a);
            vB[nt*2+e] = b; mB = fmaxf(mB, b);
        }
    }
    mA = fmaxf(mA, __shfl_xor_sync(0xffffffffu, mA, 1));
    mA = fmaxf(mA, __shfl_xor_sync(0xffffffffu, mA, 2));
    mB = fmaxf(mB, __shfl_xor_sync(0xffffffffu, mB, 1));
    mB = fmaxf(mB, __shfl_xor_sync(0xffffffffu, mB, 2));

    float sA = 0.f, sB = 0.f;
#pragma unroll
    for (int i = 0; i < 16; i++) {
        vA[i] = __expf(vA[i] - mA); sA += vA[i];
        vB[i] = __expf(vB[i] - mB); sB += vB[i];
    }
    sA += __shfl_xor_sync(0xffffffffu, sA, 1);
    sA += __shfl_xor_sync(0xffffffffu, sA, 2);
    sB += __shfl_xor_sync(0xffffffffu, sB, 1);
    sB += __shfl_xor_sync(0xffffffffu, sB, 2);
    float rAi = 1.f / sA, rBi = 1.f / sB;

#pragma unroll
    for (int nt = 0; nt < 8; nt++) {
        Ps[rA][nt*4 + t] = pack_bf16(vA[nt*2] * rAi, vA[nt*2+1] * rAi);
        Ps[rB][nt*4 + t] = pack_bf16(vB[nt*2] * rBi, vB[nt*2+1] * rBi);
    }
    __syncwarp();   // each warp reads only its own 16 Ps rows

    // ---- O = P V (64x32x64, bf16) ----
    float oacc[4][4] = {};
#pragma unroll
    for (int ks = 0; ks < 4; ks++) {
        int kp = ks * 8;
        unsigned af[4];
        ldsm_x4(af, &Ps[r0 + arow][kp + acol]);
#pragma unroll
        for (int nt = 0; nt < 4; nt++) {
            unsigned bf[2];
            bf[0] = Vs[kp + t    ][nt*8 + g];
            bf[1] = Vs[kp + t + 4][nt*8 + g];
            mma_bf16(oacc[nt], af, bf);
        }
    }

    unsigned* ob = outu + (size_t)win * 64 * 96 + head * 16;
#pragma unroll
    for (int nt = 0; nt < 4; nt++) {
        int c2 = nt*4 + t;
        ob[(size_t)rA * 96 + c2] = pack_bf16(oacc[nt][0], oacc[nt][1]);
        ob[(size_t)rB * 96 + c2] = pack_bf16(oacc[nt][2], oacc[nt][3]);
    }
}

// ---------------- launch ----------------------------------------------------
extern "C" void kernel_launch(void* const* d_in, const int* in_sizes, int n_in,
                              void* d_out, int out_size)
{
    const float* x     = (const float*)d_in[0];
    const float* y     = (const float*)d_in[1];
    const float* n1g   = (const float*)d_in[3];
    const float* n1b   = (const float*)d_in[4];
    const float* qkvw  = (const float*)d_in[5];
    const float* qkvb  = (const float*)d_in[6];
    const float* rpb   = (const float*)d_in[7];
    const float* projw = (const float*)d_in[8];
    const float* projb = (const float*)d_in[9];
    const float* n2g   = (const float*)d_in[10];
    const float* n2b   = (const float*)d_in[11];
    const float* fc1w  = (const float*)d_in[12];
    const float* fc1b  = (const float*)d_in[13];
    const float* fc2w  = (const float*)d_in[14];
    const float* fc2b  = (const float*)d_in[15];
    float* out = (float*)d_out;

    unsigned *xn, *yn, *qb, *kvb, *ao, *xn2, *hb, *wbuf;
    float *x1, *bexp;
    cudaGetSymbolAddress((void**)&xn,  g_xn);
    cudaGetSymbolAddress((void**)&yn,  g_yn);
    cudaGetSymbolAddress((void**)&qb,  g_q);
    cudaGetSymbolAddress((void**)&kvb, g_kv);
    cudaGetSymbolAddress((void**)&ao,  g_ao);
    cudaGetSymbolAddress((void**)&x1,  g_x1);
    cudaGetSymbolAddress((void**)&xn2, g_xn2);
    cudaGetSymbolAddress((void**)&hb,  g_h);
    cudaGetSymbolAddress((void**)&bexp, g_bias);
    cudaGetSymbolAddress((void**)&wbuf, g_w);

    // dynamic smem sizes: 3 stages of (As + Bs)
    const int smem24 = 3 * (128*20 + 16*(24*4 + 8)) * 4;   // 50688 B
    const int smem32 = 3 * (128*20 + 16*(32*4 + 8)) * 4;   // 56832 B
    cudaFuncSetAttribute(gemm_bf16_kernel<24,3>,
                         cudaFuncAttributeMaxDynamicSharedMemorySize, smem24);
    cudaFuncSetAttribute(gemm_bf16_kernel<32,2>,
                         cudaFuncAttributeMaxDynamicSharedMemorySize, smem32);

    // 0) weight conversion (k-pair packing, [K2][N]) + bias expansion (tiny)
    cvt_all_kernel<<<(221184 + 255) / 256, 256>>>(qkvw, projw, fc1w, fc2w, wbuf);
    bias_expand_kernel<<<NHEAD, 256>>>(rpb, bexp);

    // 1) LN1 + window permutation (bf16 out)
    ln_perm_kernel<<<TOKENS / 8, 256>>>(x, y, n1g, n1b, xn, yn);

    // 2) Q = (yn @ Wq + bq) * SCALE   -> bf16, N=192 WN24
    gemm_bf16_kernel<24,3><<<dim3(2, TOKENS / 128), 256, smem24>>>(
        yn, wbuf + WOFF_QKV, qkvb, nullptr, qb, 192, 576, 192, QSCALE, 0);
    // 3) KV = xn @ W[k|v] + b         -> bf16, N=384 WN32 (B col offset 192 uints)
    gemm_bf16_kernel<32,2><<<dim3(3, TOKENS / 128), 256, smem32>>>(
        xn, wbuf + WOFF_QKV + 192, qkvb + 192, nullptr, kvb, 192, 576, 384, 1.0f, 0);
    // 4) window attention (bf16 tensor cores)
    attn_mma_kernel<<<dim3(NWIN, NHEAD), 128>>>(qb, kvb, bexp, ao);

    // 5) x1 = x + ao @ proj_w + proj_b  (un-permute) -> fp32, N=192 WN24
    gemm_bf16_kernel<24,3><<<dim3(2, TOKENS / 128), 256, smem24>>>(
        ao, wbuf + WOFF_PROJ, projb, x, x1, 192, 192, 192, 1.0f, 1);
    // 6) LN2 (bf16 out)
    ln_kernel<<<TOKENS / 8, 256>>>(x1, n2g, n2b, xn2);

    // 7) h = gelu(xn2 @ fc1_w + fc1_b)  -> bf16, N=768 WN32
    gemm_bf16_kernel<32,2><<<dim3(6, TOKENS / 128), 256, smem32>>>(
        xn2, wbuf + WOFF_FC1, fc1b, nullptr, hb, 192, 768, 768, 1.0f, 2);
    // 8) out = x1 + h @ fc2_w + fc2_b   -> fp32, N=192 WN24, K=768
    gemm_bf16_kernel<24,3><<<dim3(2, TOKENS / 128), 256, smem24>>>(
        hb, wbuf + WOFF_FC2, fc2b, x1, out, 768, 192, 192, 1.0f, 3);
}

// round 17
// speedup vs baseline: 1.9753x; 1.0039x over previous
#include <cuda_runtime.h>
#include <math.h>

#define TOKENS 131072
#define CEMB   192
#define NHEAD  6
#define HDIM   32
#define NWIN   2048
#define QSCALE 0.17677669529663687f  // 1/sqrt(32)

// ---------------- scratch (device globals; no runtime allocation) ----------
__device__ unsigned g_xn [(size_t)TOKENS * 96];    // LN1(x), window order, bf16
__device__ unsigned g_yn [(size_t)TOKENS * 96];    // LN1(y), window order, bf16
__device__ unsigned g_q  [(size_t)TOKENS * 96];    // scaled Q, window order, bf16
__device__ unsigned g_kv [(size_t)TOKENS * 192];   // K|V, window order, bf16
__device__ unsigned g_ao [(size_t)TOKENS * 96];    // attn out, window order, bf16
__device__ float    g_x1 [(size_t)TOKENS * CEMB];  // x + proj(attn), natural, fp32
__device__ unsigned g_xn2[(size_t)TOKENS * 96];    // LN2(x1), natural, bf16
__device__ unsigned g_h  [(size_t)TOKENS * 384];   // MLP hidden, bf16
__device__ float    g_bias[NHEAD * 64 * 64];       // expanded rel-pos bias
// weights bf16, PRE-PACKED as [K/2][N] uints: elem(k2,n) = pack(W[2k2][n], W[2k2+1][n])
__device__ unsigned g_w  [221184];                 // qkv|proj|fc1|fc2

#define WOFF_QKV  0
#define WOFF_PROJ 55296
#define WOFF_FC1  73728
#define WOFF_FC2  147456

// ---------------- helpers ---------------------------------------------------
__device__ __forceinline__ unsigned pack_bf16(float lo, float hi) {
    unsigned r;
    asm("cvt.rn.bf16x2.f32 %0, %1, %2;" : "=r"(r) : "f"(hi), "f"(lo));
    return r;
}

__device__ __forceinline__ float gelu_exact(float v) {
    return 0.5f * v * (1.0f + erff(v * 0.70710678118654752f));
}

__device__ __forceinline__ void mma_bf16(float* c, const unsigned* a, const unsigned* b) {
    asm volatile(
        "mma.sync.aligned.m16n8k16.row.col.f32.bf16.bf16.f32 "
        "{%0,%1,%2,%3}, {%4,%5,%6,%7}, {%8,%9}, {%0,%1,%2,%3};"
        : "+f"(c[0]), "+f"(c[1]), "+f"(c[2]), "+f"(c[3])
        : "r"(a[0]), "r"(a[1]), "r"(a[2]), "r"(a[3]), "r"(b[0]), "r"(b[1]));
}

__device__ __forceinline__ void ldsm_x4(unsigned* r, const unsigned* smem_ptr) {
    unsigned addr = (unsigned)__cvta_generic_to_shared(smem_ptr);
    asm volatile("ldmatrix.sync.aligned.m8n8.x4.shared.b16 {%0,%1,%2,%3}, [%4];"
                 : "=r"(r[0]), "=r"(r[1]), "=r"(r[2]), "=r"(r[3]) : "r"(addr));
}

__device__ __forceinline__ void cp16(unsigned* smem_dst, const unsigned* gsrc) {
    unsigned s = (unsigned)__cvta_generic_to_shared(smem_dst);
    asm volatile("cp.async.cg.shared.global [%0], [%1], 16;" :: "r"(s), "l"(gsrc));
}
#define CP_COMMIT() asm volatile("cp.async.commit_group;")
#define CP_WAIT0()  asm volatile("cp.async.wait_group 0;")
#define CP_WAIT1()  asm volatile("cp.async.wait_group 1;")
#define CP_WAIT2()  asm volatile("cp.async.wait_group 2;")

// ---------------- fused weight conversion (one launch) ----------------------
__global__ void cvt_all_kernel(const float* __restrict__ qkvw, const float* __restrict__ projw,
                               const float* __restrict__ fc1w, const float* __restrict__ fc2w,
                               unsigned* __restrict__ dst)
{
    int i = blockIdx.x * 256 + threadIdx.x;
    const float* src; int N, base;
    if (i < 55296)       { src = qkvw;  N = 576; base = 0; }
    else if (i < 73728)  { src = projw; N = 192; base = 55296; }
    else if (i < 147456) { src = fc1w;  N = 768; base = 73728; }
    else if (i < 221184) { src = fc2w;  N = 192; base = 147456; }
    else return;
    int j = i - base;
    int k2 = j / N, n = j % N;
    dst[i] = pack_bf16(src[(size_t)(2*k2) * N + n], src[(size_t)(2*k2+1) * N + n]);
}

// ---------------- bias table expansion --------------------------------------
__global__ void bias_expand_kernel(const float* __restrict__ rpb, float* __restrict__ bias)
{
    int head = blockIdx.x;
    for (int idx = threadIdx.x; idx < 64 * 64; idx += 256) {
        int i = idx >> 6, j = idx & 63;
        int iz = i >> 4, iy = (i >> 2) & 3, ix = i & 3;
        int jz = j >> 4, jy = (j >> 2) & 3, jx = j & 3;
        int ridx = (iz - jz + 3) * 49 + (iy - jy + 3) * 7 + (ix - jx + 3);
        bias[head * 4096 + idx] = rpb[ridx * NHEAD + head];
    }
}

// ---------------- LayerNorm (float4 in, packed bf16 out) --------------------
__device__ __forceinline__ void warp_sum2(float& s, float& ss) {
#pragma unroll
    for (int o = 16; o; o >>= 1) {
        s  += __shfl_xor_sync(0xffffffffu, s,  o);
        ss += __shfl_xor_sync(0xffffffffu, ss, o);
    }
}

__device__ __forceinline__ void ln_row_f4(
    const float4* __restrict__ in, unsigned* __restrict__ outu,
    float4 g0, float4 b0, float4 g1, float4 b1, int lane, bool hi)
{
    float4 a = in[lane];
    float4 c = hi ? in[32 + lane] : make_float4(0.f, 0.f, 0.f, 0.f);
    float s  = a.x + a.y + a.z + a.w + c.x + c.y + c.z + c.w;
    float ss = a.x*a.x + a.y*a.y + a.z*a.z + a.w*a.w
             + c.x*c.x + c.y*c.y + c.z*c.z + c.w*c.w;
    warp_sum2(s, ss);
    float mean = s * (1.f/192.f);
    float var  = ss * (1.f/192.f) - mean * mean;
    float r = rsqrtf(var + 1e-5f);
    uint2 o;
    o.x = pack_bf16((a.x - mean) * r * g0.x + b0.x, (a.y - mean) * r * g0.y + b0.y);
    o.y = pack_bf16((a.z - mean) * r * g0.z + b0.z, (a.w - mean) * r * g0.w + b0.w);
    *(uint2*)&outu[lane * 2] = o;
    if (hi) {
        uint2 p;
        p.x = pack_bf16((c.x - mean) * r * g1.x + b1.x, (c.y - mean) * r * g1.y + b1.y);
        p.y = pack_bf16((c.z - mean) * r * g1.z + b1.z, (c.w - mean) * r * g1.w + b1.w);
        *(uint2*)&outu[64 + lane * 2] = p;
    }
}

__global__ void __launch_bounds__(256) ln_perm_kernel(
    const float* __restrict__ x, const float* __restrict__ y,
    const float* __restrict__ g, const float* __restrict__ b,
    unsigned* __restrict__ xn, unsigned* __restrict__ yn)
{
    int token = blockIdx.x * 8 + (threadIdx.x >> 5);
    int lane  = threadIdx.x & 31;
    bool hi = lane < 16;
    int w = token & 63, h = (token >> 6) & 63, d = token >> 12;
    int win  = (((d >> 2) << 4) + (h >> 2)) * 16 + (w >> 2);
    int pos  = ((d & 3) << 4) + ((h & 3) << 2) + (w & 3);
    size_t prow = (size_t)win * 64 + pos;

    const float4* g4 = (const float4*)g;
    const float4* b4 = (const float4*)b;
    float4 g0 = g4[lane], b0 = b4[lane];
    float4 g1 = make_float4(0,0,0,0), b1 = g1;
    if (hi) { g1 = g4[32 + lane]; b1 = b4[32 + lane]; }

    ln_row_f4((const float4*)(x + (size_t)token * CEMB), xn + prow * 96,
              g0, b0, g1, b1, lane, hi);
    ln_row_f4((const float4*)(y + (size_t)token * CEMB), yn + prow * 96,
              g0, b0, g1, b1, lane, hi);
}

__global__ void __launch_bounds__(256) ln_kernel(
    const float* __restrict__ x, const float* __restrict__ g, const float* __restrict__ b,
    unsigned* __restrict__ xn)
{
    int token = blockIdx.x * 8 + (threadIdx.x >> 5);
    int lane  = threadIdx.x & 31;
    bool hi = lane < 16;
    const float4* g4 = (const float4*)g;
    const float4* b4 = (const float4*)b;
    float4 g0 = g4[lane], b0 = b4[lane];
    float4 g1 = make_float4(0,0,0,0), b1 = g1;
    if (hi) { g1 = g4[32 + lane]; b1 = b4[32 + lane]; }
    ln_row_f4((const float4*)(x + (size_t)token * CEMB), xn + (size_t)token * 96,
              g0, b0, g1, b1, lane, hi);
}

// ---------------- bf16 GEMM, 4-stage cp.async pipeline + LDSM ---------------
// A: bf16 packed [M, K/2] uints. B: bf16 PRE-PACKED [K/2, N] uints (k-pairs).
// CTA tile 128 x (4*WN); 256 threads = 8 warps (2x4), warp 64 x WN.
// mode 0: bf16 C=(acc+bias)*scale; 1: f32 C[perm]=..+resid; 2: bf16 gelu; 3: f32 +resid
template<int WN, int MINB>
__global__ void __launch_bounds__(256, MINB) gemm_bf16_kernel(
    const unsigned* __restrict__ Au, const unsigned* __restrict__ Bu,
    const float* __restrict__ bias, const float* __restrict__ resid,
    void* __restrict__ Cout,
    int K, int ldb2, int ldc, float scale, int mode)
{
    constexpr int BN  = WN * 4;
    constexpr int LDB = BN + 8;         // uints; ≡8 mod 32 -> conflict-free frag reads
    constexpr int NF  = WN / 8;
    constexpr int NBC = 16 * (BN / 4);  // B 16-byte chunks per tile
    constexpr int BT  = (NBC + 255) / 256;  // B tasks per thread (<=2)
    constexpr int ASZ = 128 * 20;
    constexpr int BSZ = 16 * LDB;
    constexpr int STG = ASZ + BSZ;

    extern __shared__ unsigned smem[];  // 4 stages of [As | Bs]

    int tid = threadIdx.x;
    int wid = tid >> 5, lane = tid & 31;
    int g = lane >> 2, t = lane & 3;
    int wm = (wid >> 2) * 64;
    int wn = (wid & 3) * WN;
    size_t rowBase = (size_t)blockIdx.y * 128;
    int nb = blockIdx.x * BN;
    int K2 = K >> 1;

    int arow = (lane & 7) + ((lane >> 3) & 1) * 8;   // ldmatrix lane addressing
    int acol = ((lane >> 4) & 1) * 4;

    // hoisted A staging indices
    int ar[2], ac4[2];
#pragma unroll
    for (int it = 0; it < 2; it++) { int idx = tid + 256*it; ar[it] = idx >> 2; ac4[it] = (idx & 3) * 4; }
    // hoisted B staging indices (kill div/mod in the hot loop)
    int bbr[BT], bbc[BT]; bool bok[BT];
#pragma unroll
    for (int it = 0; it < BT; it++) {
        int t2 = tid + 256*it;
        bok[it] = t2 < NBC;
        int tc = bok[it] ? t2 : 0;
        bbr[it] = tc / (BN/4);
        bbc[it] = (tc % (BN/4)) * 4;
    }

    const unsigned* Abase = Au + rowBase * K2;
    const unsigned* Bbase = Bu + nb;

    int NIT = K >> 5;

    auto stage_in = [&](int tile, unsigned* As) {
        unsigned* Bsp = As + ASZ;
        int kn2 = tile * 16;
#pragma unroll
        for (int it = 0; it < 2; it++)
            cp16(&As[ar[it]*20 + ac4[it]], Abase + (size_t)ar[it] * K2 + kn2 + ac4[it]);
#pragma unroll
        for (int it = 0; it < BT; it++)
            if (bok[it])
                cp16(&Bsp[bbr[it]*LDB + bbc[it]], Bbase + (size_t)(kn2 + bbr[it]) * ldb2 + bbc[it]);
    };

    // prologue: stage tiles 0..2 (NIT >= 6 always)
    stage_in(0, smem);           CP_COMMIT();
    stage_in(1, smem + STG);     CP_COMMIT();
    stage_in(2, smem + 2*STG);   CP_COMMIT();

    float acc[4][NF][4] = {};

    for (int i = 0; i < NIT; i++) {
        if (i + 2 < NIT)      { CP_WAIT2(); }
        else if (i + 1 < NIT) { CP_WAIT1(); }
        else                  { CP_WAIT0(); }
        __syncthreads();

        const unsigned* Asb = smem + (i & 3) * STG;
        const unsigned* Bsb = Asb + ASZ;

#pragma unroll
        for (int ks = 0; ks < 2; ks++) {
            int kp = ks * 8;
            unsigned bf[NF][2];
#pragma unroll
            for (int nf = 0; nf < NF; nf++) {
                bf[nf][0] = Bsb[(kp + t    )*LDB + wn + nf*8 + g];
                bf[nf][1] = Bsb[(kp + t + 4)*LDB + wn + nf*8 + g];
            }
#pragma unroll
            for (int mf = 0; mf < 4; mf++) {
                unsigned af[4];
                ldsm_x4(af, &Asb[(wm + mf*16 + arow)*20 + kp + acol]);
#pragma unroll
                for (int nf = 0; nf < NF; nf++) mma_bf16(acc[mf][nf], af, bf[nf]);
            }
        }

        if (i + 3 < NIT) {
            stage_in(i + 3, smem + ((i + 3) & 3) * STG);
            CP_COMMIT();
        }
    }

#pragma unroll
    for (int mf = 0; mf < 4; mf++) {
#pragma unroll
        for (int half = 0; half < 2; half++) {
            size_t row = rowBase + wm + mf*16 + g + half*8;
            size_t orow = row;
            if (mode == 1) {
                int win = (int)(row >> 6), pos = (int)(row & 63);
                int wd = win >> 8, wh = (win >> 4) & 15, ww = win & 15;
                int d = (wd << 2) + (pos >> 4);
                int h = (wh << 2) + ((pos >> 2) & 3);
                int w = (ww << 2) + (pos & 3);
                orow = ((size_t)(d * 64 + h)) * 64 + w;
            }
#pragma unroll
            for (int nf = 0; nf < NF; nf++) {
                int col = nb + wn + nf*8 + 2*t;
                float2 bb = *(const float2*)(bias + col);
                float v0 = acc[mf][nf][half*2+0] + bb.x;
                float v1 = acc[mf][nf][half*2+1] + bb.y;
                if (mode == 0) {
                    ((unsigned*)Cout)[(orow * (size_t)ldc + col) >> 1] =
                        pack_bf16(v0 * scale, v1 * scale);
                } else if (mode == 2) {
                    ((unsigned*)Cout)[(orow * (size_t)ldc + col) >> 1] =
                        pack_bf16(gelu_exact(v0), gelu_exact(v1));
                } else {
                    float2 rs = *(const float2*)(resid + (mode == 1 ? orow : row) * CEMB + col);
                    float2 o = make_float2(v0 + rs.x, v1 + rs.y);
                    *(float2*)((float*)Cout + orow * (size_t)ldc + col) = o;
                }
            }
        }
    }
}

// ---------------- bf16 tensor-core windowed cross-attention -----------------
// one block per (window, head); 128 threads (4 warps, 16 rows each). bf16 I/O.
__global__ void __launch_bounds__(128) attn_mma_kernel(
    const unsigned* __restrict__ qu, const unsigned* __restrict__ kvu,
    const float* __restrict__ bias, unsigned* __restrict__ outu)
{
    __shared__ unsigned sm_a[64 * 20 * 2];   // Qs | Ks; reused as Ps[64][36]
    __shared__ unsigned sm_v[32 * 40];

    unsigned (*Qs)[20] = (unsigned(*)[20])sm_a;
    unsigned (*Ks)[20] = (unsigned(*)[20])(sm_a + 64*20);
    unsigned (*Ps)[36] = (unsigned(*)[36])sm_a;   // 64*36 = 2304 <= 2560
    unsigned (*Vs)[40] = (unsigned(*)[40])sm_v;   // [j2][d], pairs along j

    int win = blockIdx.x, head = blockIdx.y;
    int tid = threadIdx.x;
    int wid = tid >> 5, lane = tid & 31;
    int g = lane >> 2, t = lane & 3;
    int arow = (lane & 7) + ((lane >> 3) & 1) * 8;
    int acol = ((lane >> 4) & 1) * 4;

    const unsigned* qb = qu  + (size_t)win * 64 * 96  + head * 16;
    const unsigned* kb = kvu + (size_t)win * 64 * 192 + head * 16;
    const unsigned* vb = kb + 96;

    for (int idx = tid; idx < 64 * 8; idx += 128) {
        int r = idx >> 3, u2 = (idx & 7) * 2;
        *(uint2*)&Qs[r][u2] = *(const uint2*)(qb + (size_t)r * 96  + u2);
        *(uint2*)&Ks[r][u2] = *(const uint2*)(kb + (size_t)r * 192 + u2);
    }
    for (int idx = tid; idx < 32 * 16; idx += 128) {
        int j2 = idx >> 4, c2 = idx & 15;
        unsigned ue = vb[(size_t)(2*j2    ) * 192 + c2];
        unsigned uo = vb[(size_t)(2*j2 + 1) * 192 + c2];
        Vs[j2][2*c2    ] = __byte_perm(ue, uo, 0x5410);
        Vs[j2][2*c2 + 1] = __byte_perm(ue, uo, 0x7632);
    }
    __syncthreads();

    // ---- S = Q K^T (64x64x32, bf16) ----
    int r0 = wid * 16;
    float sacc[8][4] = {};
#pragma unroll
    for (int ks = 0; ks < 2; ks++) {
        int kp = ks * 8;
        unsigned af[4];
        ldsm_x4(af, &Qs[r0 + arow][kp + acol]);
#pragma unroll
        for (int nt = 0; nt < 8; nt++) {
            unsigned bf[2];
            bf[0] = Ks[nt*8 + g][kp + t];
            bf[1] = Ks[nt*8 + g][kp + t + 4];
            mma_bf16(sacc[nt], af, bf);
        }
    }
    __syncthreads();   // all warps done with Qs/Ks before Ps overwrites

    // ---- bias + softmax (rows rA, rB) ----
    int rA = r0 + g, rB = rA + 8;
    const float* bA = bias + head * 4096 + rA * 64;
    const float* bB = bias + head * 4096 + rB * 64;

    float vA[16], vB[16];
    float mA = -1e30f, mB = -1e30f;
#pragma unroll
    for (int nt = 0; nt < 8; nt++) {
#pragma unroll
        for (int e = 0; e < 2; e++) {
            int j = nt*8 + 2*t + e;
            float a = sacc[nt][e]     + bA[j];
            float b = sacc[nt][2 + e] + bB[j];
            vA[nt*2+e] = a; mA = fmaxf(mA, a);
            vB[nt*2+e] = b; mB = fmaxf(mB, b);
        }
    }
    mA = fmaxf(mA, __shfl_xor_sync(0xffffffffu, mA, 1));
    mA = fmaxf(mA, __shfl_xor_sync(0xffffffffu, mA, 2));
    mB = fmaxf(mB, __shfl_xor_sync(0xffffffffu, mB, 1));
    mB = fmaxf(mB, __shfl_xor_sync(0xffffffffu, mB, 2));

    float sA = 0.f, sB = 0.f;
#pragma unroll
    for (int i = 0; i < 16; i++) {
        vA[i] = __expf(vA[i] - mA); sA += vA[i];
        vB[i] = __expf(vB[i] - mB); sB += vB[i];
    }
    sA += __shfl_xor_sync(0xffffffffu, sA, 1);
    sA += __shfl_xor_sync(0xffffffffu, sA, 2);
    sB += __shfl_xor_sync(0xffffffffu, sB, 1);
    sB += __shfl_xor_sync(0xffffffffu, sB, 2);
    float rAi = 1.f / sA, rBi = 1.f / sB;

#pragma unroll
    for (int nt = 0; nt < 8; nt++) {
        Ps[rA][nt*4 + t] = pack_bf16(vA[nt*2] * rAi, vA[nt*2+1] * rAi);
        Ps[rB][nt*4 + t] = pack_bf16(vB[nt*2] * rBi, vB[nt*2+1] * rBi);
    }
    __syncwarp();   // each warp reads only its own 16 Ps rows

    // ---- O = P V (64x32x64, bf16) ----
    float oacc[4][4] = {};
#pragma unroll
    for (int ks = 0; ks < 4; ks++) {
        int kp = ks * 8;
        unsigned af[4];
        ldsm_x4(af, &Ps[r0 + arow][kp + acol]);
#pragma unroll
        for (int nt = 0; nt < 4; nt++) {
            unsigned bf[2];
            bf[0] = Vs[kp + t    ][nt*8 + g];
            bf[1] = Vs[kp + t + 4][nt*8 + g];
            mma_bf16(oacc[nt], af, bf);
        }
    }

    unsigned* ob = outu + (size_t)win * 64 * 96 + head * 16;
#pragma unroll
    for (int nt = 0; nt < 4; nt++) {
        int c2 = nt*4 + t;
        ob[(size_t)rA * 96 + c2] = pack_bf16(oacc[nt][0], oacc[nt][1]);
        ob[(size_t)rB * 96 + c2] = pack_bf16(oacc[nt][2], oacc[nt][3]);
    }
}

// ---------------- launch ----------------------------------------------------
extern "C" void kernel_launch(void* const* d_in, const int* in_sizes, int n_in,
                              void* d_out, int out_size)
{
    const float* x     = (const float*)d_in[0];
    const float* y     = (const float*)d_in[1];
    const float* n1g   = (const float*)d_in[3];
    const float* n1b   = (const float*)d_in[4];
    const float* qkvw  = (const float*)d_in[5];
    const float* qkvb  = (const float*)d_in[6];
    const float* rpb   = (const float*)d_in[7];
    const float* projw = (const float*)d_in[8];
    const float* projb = (const float*)d_in[9];
    const float* n2g   = (const float*)d_in[10];
    const float* n2b   = (const float*)d_in[11];
    const float* fc1w  = (const float*)d_in[12];
    const float* fc1b  = (const float*)d_in[13];
    const float* fc2w  = (const float*)d_in[14];
    const float* fc2b  = (const float*)d_in[15];
    float* out = (float*)d_out;

    unsigned *xn, *yn, *qb, *kvb, *ao, *xn2, *hb, *wbuf;
    float *x1, *bexp;
    cudaGetSymbolAddress((void**)&xn,  g_xn);
    cudaGetSymbolAddress((void**)&yn,  g_yn);
    cudaGetSymbolAddress((void**)&qb,  g_q);
    cudaGetSymbolAddress((void**)&kvb, g_kv);
    cudaGetSymbolAddress((void**)&ao,  g_ao);
    cudaGetSymbolAddress((void**)&x1,  g_x1);
    cudaGetSymbolAddress((void**)&xn2, g_xn2);
    cudaGetSymbolAddress((void**)&hb,  g_h);
    cudaGetSymbolAddress((void**)&bexp, g_bias);
    cudaGetSymbolAddress((void**)&wbuf, g_w);

    // dynamic smem sizes: 4 stages of (As + Bs)
    const int smem24 = 4 * (128*20 + 16*(24*4 + 8)) * 4;   // 67584 B
    const int smem32 = 4 * (128*20 + 16*(32*4 + 8)) * 4;   // 75776 B
    cudaFuncSetAttribute(gemm_bf16_kernel<24,3>,
                         cudaFuncAttributeMaxDynamicSharedMemorySize, smem24);
    cudaFuncSetAttribute(gemm_bf16_kernel<32,2>,
                         cudaFuncAttributeMaxDynamicSharedMemorySize, smem32);

    // 0) weight conversion (k-pair packing, [K2][N]) + bias expansion (tiny)
    cvt_all_kernel<<<(221184 + 255) / 256, 256>>>(qkvw, projw, fc1w, fc2w, wbuf);
    bias_expand_kernel<<<NHEAD, 256>>>(rpb, bexp);

    // 1) LN1 + window permutation (bf16 out)
    ln_perm_kernel<<<TOKENS / 8, 256>>>(x, y, n1g, n1b, xn, yn);

    // 2) Q = (yn @ Wq + bq) * SCALE   -> bf16, N=192 WN24
    gemm_bf16_kernel<24,3><<<dim3(2, TOKENS / 128), 256, smem24>>>(
        yn, wbuf + WOFF_QKV, qkvb, nullptr, qb, 192, 576, 192, QSCALE, 0);
    // 3) KV = xn @ W[k|v] + b         -> bf16, N=384 WN32 (B col offset 192 uints)
    gemm_bf16_kernel<32,2><<<dim3(3, TOKENS / 128), 256, smem32>>>(
        xn, wbuf + WOFF_QKV + 192, qkvb + 192, nullptr, kvb, 192, 576, 384, 1.0f, 0);
    // 4) window attention (bf16 tensor cores)
    attn_mma_kernel<<<dim3(NWIN, NHEAD), 128>>>(qb, kvb, bexp, ao);

    // 5) x1 = x + ao @ proj_w + proj_b  (un-permute) -> fp32, N=192 WN24
    gemm_bf16_kernel<24,3><<<dim3(2, TOKENS / 128), 256, smem24>>>(
        ao, wbuf + WOFF_PROJ, projb, x, x1, 192, 192, 192, 1.0f, 1);
    // 6) LN2 (bf16 out)
    ln_kernel<<<TOKENS / 8, 256>>>(x1, n2g, n2b, xn2);

    // 7) h = gelu(xn2 @ fc1_w + fc1_b)  -> bf16, N=768 WN32
    gemm_bf16_kernel<32,2><<<dim3(6, TOKENS / 128), 256, smem32>>>(
        xn2, wbuf + WOFF_FC1, fc1b, nullptr, hb, 192, 768, 768, 1.0f, 2);
    // 8) out = x1 + h @ fc2_w + fc2_b   -> fp32, N=192 WN24, K=768
    gemm_bf16_kernel<24,3><<<dim3(2, TOKENS / 128), 256, smem24>>>(
        hb, wbuf + WOFF_FC2, fc2b, x1, out, 768, 192, 192, 1.0f, 3);
}